// round 1
// baseline (speedup 1.0000x reference)
#include <cuda_runtime.h>
#include <cuda_bf16.h>

#define BATCH 8
#define SEQLEN 1024
#define DIN 512
#define NHEAD 8
#define HDIM 64
#define DOUT 512   // NHEAD * HDIM

// Head-major scratch: [B, H, L, 64] each. 16 MB each, 48 MB total (static, no alloc).
__device__ float g_q[BATCH * NHEAD * SEQLEN * HDIM];
__device__ float g_k[BATCH * NHEAD * SEQLEN * HDIM];
__device__ float g_v[BATCH * NHEAD * SEQLEN * HDIM];

// ---------------------------------------------------------------------------
// Projection GEMM: out[b,h,l,d] = sum_k X[b*L+l, k] * W[k, h*64+d]  (* scale)
// M = B*L = 8192, N = 512, K = 512.  BM=BN=64, BK=16, 256 threads, 4x4 frags.
// ---------------------------------------------------------------------------
__global__ __launch_bounds__(256) void proj_kernel(
    const float* __restrict__ X, const float* __restrict__ W,
    int which, float scale)
{
    float* out = (which == 0) ? g_q : (which == 1) ? g_k : g_v;

    __shared__ float sA[16][64];   // [k][m] (transposed store)
    __shared__ float sB[16][64];   // [k][n]

    const int t  = threadIdx.x;
    const int tx = t & 15;         // 0..15 -> n frag
    const int ty = t >> 4;         // 0..15 -> m frag
    const int m0 = blockIdx.y * 64;
    const int n0 = blockIdx.x * 64;

    const int arow = t >> 2;       // 0..63
    const int ac4  = t & 3;        // 0..3   (A row has 16 floats per k-slab)
    const int brow = t >> 4;       // 0..15
    const int bc4  = t & 15;       // 0..15

    float acc[4][4];
#pragma unroll
    for (int i = 0; i < 4; i++)
#pragma unroll
        for (int j = 0; j < 4; j++) acc[i][j] = 0.f;

    for (int kk = 0; kk < DIN; kk += 16) {
        float4 av = *(const float4*)&X[(m0 + arow) * DIN + kk + ac4 * 4];
        sA[ac4 * 4 + 0][arow] = av.x;
        sA[ac4 * 4 + 1][arow] = av.y;
        sA[ac4 * 4 + 2][arow] = av.z;
        sA[ac4 * 4 + 3][arow] = av.w;
        *(float4*)&sB[brow][bc4 * 4] =
            *(const float4*)&W[(kk + brow) * DOUT + n0 + bc4 * 4];
        __syncthreads();

#pragma unroll
        for (int k = 0; k < 16; k++) {
            float4 a4 = *(const float4*)&sA[k][ty * 4];
            float4 b4 = *(const float4*)&sB[k][tx * 4];
            float ar[4] = {a4.x, a4.y, a4.z, a4.w};
            float br[4] = {b4.x, b4.y, b4.z, b4.w};
#pragma unroll
            for (int i = 0; i < 4; i++)
#pragma unroll
                for (int j = 0; j < 4; j++) acc[i][j] += ar[i] * br[j];
        }
        __syncthreads();
    }

    // Write head-major: row m -> (b, l); col n -> (h, d). 4 consecutive n stay
    // inside one head (n0+tx*4 is 4-aligned, head width 64).
    const int nbase = n0 + tx * 4;
    const int h = nbase >> 6;
    const int d = nbase & 63;
#pragma unroll
    for (int i = 0; i < 4; i++) {
        int m = m0 + ty * 4 + i;
        int b = m >> 10;
        int l = m & 1023;
        float4 o = make_float4(acc[i][0] * scale, acc[i][1] * scale,
                               acc[i][2] * scale, acc[i][3] * scale);
        *(float4*)&out[(((b * NHEAD + h) * SEQLEN) + l) * HDIM + d] = o;
    }
}

// ---------------------------------------------------------------------------
// Flash attention (causal): one thread = one query row. Block = 128 queries
// of one (b,h). Key/value tiles of 32 rows staged in smem.
// ---------------------------------------------------------------------------
__global__ __launch_bounds__(128) void attn_kernel(float* __restrict__ out)
{
    const int bh  = blockIdx.y;              // b*NHEAD + h
    const int q0  = blockIdx.x * 128;
    const int tid = threadIdx.x;
    const int qi  = q0 + tid;

    __shared__ float sK[32][64];
    __shared__ float sV[32][64];

    const float* __restrict__ Qb = g_q + (size_t)bh * SEQLEN * HDIM;
    const float* __restrict__ Kb = g_k + (size_t)bh * SEQLEN * HDIM;
    const float* __restrict__ Vb = g_v + (size_t)bh * SEQLEN * HDIM;

    float q[64];
#pragma unroll
    for (int d4 = 0; d4 < 16; d4++) {
        float4 v = *(const float4*)&Qb[qi * HDIM + d4 * 4];
        q[d4 * 4 + 0] = v.x; q[d4 * 4 + 1] = v.y;
        q[d4 * 4 + 2] = v.z; q[d4 * 4 + 3] = v.w;
    }

    float o[64];
#pragma unroll
    for (int d = 0; d < 64; d++) o[d] = 0.f;
    float mrun = -1e30f, lsum = 0.f;

    const int kend = q0 + 128;               // max key needed by this block (+1)
    for (int k0 = 0; k0 < kend; k0 += 32) {
        __syncthreads();                     // protect prev-iter smem reads
#pragma unroll
        for (int i = 0; i < 4; i++) {
            int idx = tid + i * 128;         // 0..511 float4 slots
            int r   = idx >> 4;
            int c4  = idx & 15;
            *(float4*)&sK[r][c4 * 4] =
                *(const float4*)&Kb[(k0 + r) * HDIM + c4 * 4];
            *(float4*)&sV[r][c4 * 4] =
                *(const float4*)&Vb[(k0 + r) * HDIM + c4 * 4];
        }
        __syncthreads();

        float sc[32];
        float tmax = -1e30f;
#pragma unroll
        for (int kk = 0; kk < 32; kk++) {
            float s = 0.f;
#pragma unroll
            for (int d4 = 0; d4 < 16; d4++) {
                float4 kv = *(const float4*)&sK[kk][d4 * 4];
                s += q[d4 * 4 + 0] * kv.x + q[d4 * 4 + 1] * kv.y
                   + q[d4 * 4 + 2] * kv.z + q[d4 * 4 + 3] * kv.w;
            }
            if (k0 + kk > qi) s = -1e30f;    // causal mask
            sc[kk] = s;
            tmax = fmaxf(tmax, s);
        }

        float mnew = fmaxf(mrun, tmax);
        float corr = __expf(mrun - mnew);    // exp(-inf)=0 on first tile
        mrun = mnew;
        lsum *= corr;
#pragma unroll
        for (int d = 0; d < 64; d++) o[d] *= corr;

#pragma unroll
        for (int kk = 0; kk < 32; kk++) {
            float p = __expf(sc[kk] - mrun); // masked -> underflow -> 0
            lsum += p;
#pragma unroll
            for (int d4 = 0; d4 < 16; d4++) {
                float4 vv = *(const float4*)&sV[kk][d4 * 4];
                o[d4 * 4 + 0] += p * vv.x;
                o[d4 * 4 + 1] += p * vv.y;
                o[d4 * 4 + 2] += p * vv.z;
                o[d4 * 4 + 3] += p * vv.w;
            }
        }
    }

    const float inv = 1.f / lsum;
    const int b = bh >> 3;
    const int h = bh & 7;
    float* orow = out + ((size_t)(b * SEQLEN + qi) * DOUT) + h * HDIM;
#pragma unroll
    for (int d4 = 0; d4 < 16; d4++) {
        float4 v = make_float4(o[d4 * 4 + 0] * inv, o[d4 * 4 + 1] * inv,
                               o[d4 * 4 + 2] * inv, o[d4 * 4 + 3] * inv);
        *(float4*)&orow[d4 * 4] = v;
    }
}

extern "C" void kernel_launch(void* const* d_in, const int* in_sizes, int n_in,
                              void* d_out, int out_size)
{
    const float* Qs = (const float*)d_in[0];
    const float* Ks = (const float*)d_in[1];
    const float* Vs = (const float*)d_in[2];
    const float* WQ = (const float*)d_in[3];
    const float* WK = (const float*)d_in[4];
    const float* WV = (const float*)d_in[5];
    float* out = (float*)d_out;

    dim3 pgrid(DOUT / 64, (BATCH * SEQLEN) / 64);   // (8, 128)
    proj_kernel<<<pgrid, 256>>>(Qs, WQ, 0, 0.125f); // scale = 1/sqrt(64)
    proj_kernel<<<pgrid, 256>>>(Ks, WK, 1, 1.0f);
    proj_kernel<<<pgrid, 256>>>(Vs, WV, 2, 1.0f);

    dim3 agrid(SEQLEN / 128, BATCH * NHEAD);        // (8, 64)
    attn_kernel<<<agrid, 128>>>(out);
}

// round 4
// speedup vs baseline: 1.1954x; 1.1954x over previous
#include <cuda_runtime.h>
#include <cuda_bf16.h>
#include <cstdint>

#define BATCH 8
#define SEQLEN 1024
#define DIN 512
#define NHEAD 8
#define HDIM 64
#define DOUT 512
#define MTOT (BATCH * SEQLEN)   // 8192

// ---------------------------------------------------------------------------
// Static device scratch (no runtime allocation allowed)
// ---------------------------------------------------------------------------
__device__ __align__(16) float g_q[BATCH * NHEAD * SEQLEN * HDIM];
__device__ __align__(16) float g_k[BATCH * NHEAD * SEQLEN * HDIM];
__device__ __align__(16) float g_v[BATCH * NHEAD * SEQLEN * HDIM];

// bf16 hi/lo splits of the three input sequences: [sel][m*DIN + k]
__device__ __align__(16) __nv_bfloat16 g_xhi[3 * MTOT * DIN];
__device__ __align__(16) __nv_bfloat16 g_xlo[3 * MTOT * DIN];
// transposed weights, K-major: [sel][n*DIN + k]
__device__ __align__(16) __nv_bfloat16 g_wthi[3 * DOUT * DIN];
__device__ __align__(16) __nv_bfloat16 g_wtlo[3 * DOUT * DIN];

__device__ __forceinline__ void split_bf16(float x, __nv_bfloat16& h, __nv_bfloat16& l) {
    h = __float2bfloat16(x);
    l = __float2bfloat16(x - __bfloat162float(h));
}

// mma.sync m16n8k16 bf16 -> fp32 (base-target compatible, runs on tensor pipe)
__device__ __forceinline__ void mma16816(float* c, const uint32_t* a, const uint32_t* b) {
    asm volatile(
        "mma.sync.aligned.m16n8k16.row.col.f32.bf16.bf16.f32 "
        "{%0,%1,%2,%3}, {%4,%5,%6,%7}, {%8,%9}, {%0,%1,%2,%3};"
        : "+f"(c[0]), "+f"(c[1]), "+f"(c[2]), "+f"(c[3])
        : "r"(a[0]), "r"(a[1]), "r"(a[2]), "r"(a[3]), "r"(b[0]), "r"(b[1]));
}

// ---------------------------------------------------------------------------
// Conversion: X (fp32) -> bf16 hi/lo
// ---------------------------------------------------------------------------
__global__ __launch_bounds__(256) void convert_x(
    const float* __restrict__ x0, const float* __restrict__ x1,
    const float* __restrict__ x2)
{
    const int sel = blockIdx.y;
    const float* __restrict__ x = (sel == 0) ? x0 : (sel == 1) ? x1 : x2;
    const int i = blockIdx.x * 256 + threadIdx.x;          // float4 index
    float4 v = ((const float4*)x)[i];
    __nv_bfloat16 h0, h1, h2, h3, l0, l1, l2, l3;
    split_bf16(v.x, h0, l0); split_bf16(v.y, h1, l1);
    split_bf16(v.z, h2, l2); split_bf16(v.w, h3, l3);
    const size_t e = (size_t)sel * (MTOT * DIN) + (size_t)i * 4;
    *(__nv_bfloat162*)&g_xhi[e]     = __nv_bfloat162(h0, h1);
    *(__nv_bfloat162*)&g_xhi[e + 2] = __nv_bfloat162(h2, h3);
    *(__nv_bfloat162*)&g_xlo[e]     = __nv_bfloat162(l0, l1);
    *(__nv_bfloat162*)&g_xlo[e + 2] = __nv_bfloat162(l2, l3);
}

// ---------------------------------------------------------------------------
// Conversion: W [k][n] fp32 -> transposed bf16 hi/lo [n][k]
// ---------------------------------------------------------------------------
__global__ __launch_bounds__(256) void convert_wt(
    const float* __restrict__ w0, const float* __restrict__ w1,
    const float* __restrict__ w2)
{
    const int sel = blockIdx.z;
    const float* __restrict__ W = (sel == 0) ? w0 : (sel == 1) ? w1 : w2;
    __shared__ float tile[32][33];
    const int n0 = blockIdx.x * 32, k0 = blockIdx.y * 32;
    const int tx = threadIdx.x, ty = threadIdx.y;   // (32, 8)
#pragma unroll
    for (int i = 0; i < 32; i += 8)
        tile[ty + i][tx] = W[(k0 + ty + i) * DOUT + n0 + tx];
    __syncthreads();
    const size_t base = (size_t)sel * (DOUT * DIN);
#pragma unroll
    for (int i = 0; i < 32; i += 8) {
        int n = ty + i;
        float v = tile[tx][n];                      // = W[k0+tx][n0+n]
        __nv_bfloat16 h, l;
        split_bf16(v, h, l);
        g_wthi[base + (size_t)(n0 + n) * DIN + k0 + tx] = h;
        g_wtlo[base + (size_t)(n0 + n) * DIN + k0 + tx] = l;
    }
}

// ---------------------------------------------------------------------------
// Projection GEMM via mma.sync bf16-split.
// C[8192,512] = X[8192,512] @ W[512,512], 3-pass hi/lo, fp32 accum.
// Block tile 128x128, BK=32, 256 threads = 8 warps (2m x 4n), warp tile 64x32.
// ---------------------------------------------------------------------------
#define PADK 40   // bf16 row stride for a 32-wide K slab (conflict-free frags)

__global__ __launch_bounds__(256) void proj_mma_sync()
{
    __shared__ __nv_bfloat16 sAh[128 * PADK];
    __shared__ __nv_bfloat16 sAl[128 * PADK];
    __shared__ __nv_bfloat16 sBh[128 * PADK];
    __shared__ __nv_bfloat16 sBl[128 * PADK];

    const int sel = blockIdx.z;
    const int n0  = blockIdx.x * 128;
    const int m0  = blockIdx.y * 128;
    const int tid = threadIdx.x;
    const int w   = tid >> 5;
    const int lane = tid & 31;
    const int wm = w >> 2;        // 0..1  (64-row slice)
    const int wn = w & 3;         // 0..3  (32-col slice)
    const int lr = lane >> 2;     // 0..7
    const int lc = lane & 3;      // 0..3

    const __nv_bfloat16* __restrict__ Ahp = g_xhi + (size_t)sel * (MTOT * DIN);
    const __nv_bfloat16* __restrict__ Alp = g_xlo + (size_t)sel * (MTOT * DIN);
    const __nv_bfloat16* __restrict__ Bhp = g_wthi + (size_t)sel * (DOUT * DIN);
    const __nv_bfloat16* __restrict__ Blp = g_wtlo + (size_t)sel * (DOUT * DIN);

    float acc[4][4][4];
#pragma unroll
    for (int i = 0; i < 4; i++)
#pragma unroll
        for (int j = 0; j < 4; j++)
#pragma unroll
            for (int r = 0; r < 4; r++) acc[i][j][r] = 0.f;

    for (int kk = 0; kk < DIN; kk += 32) {
        // ---- stage loads: each tile is 128 rows x 4 uint4 (32 bf16) ----
#pragma unroll
        for (int i = 0; i < 2; i++) {
            int idx = tid + i * 256;           // 0..511
            int r = idx >> 2;
            int c = idx & 3;
            size_t ga = (size_t)(m0 + r) * DIN + kk + c * 8;
            size_t gb = (size_t)(n0 + r) * DIN + kk + c * 8;
            *(uint4*)&sAh[r * PADK + c * 8] = *(const uint4*)&Ahp[ga];
            *(uint4*)&sAl[r * PADK + c * 8] = *(const uint4*)&Alp[ga];
            *(uint4*)&sBh[r * PADK + c * 8] = *(const uint4*)&Bhp[gb];
            *(uint4*)&sBl[r * PADK + c * 8] = *(const uint4*)&Blp[gb];
        }
        __syncthreads();

#pragma unroll
        for (int ks = 0; ks < 2; ks++) {
            const int k0 = ks * 16;
            // B fragments (hi and lo), 4 n8 tiles
            uint32_t bH[4][2], bL[4][2];
#pragma unroll
            for (int nt = 0; nt < 4; nt++) {
                int cb = wn * 32 + nt * 8 + lr;
                bH[nt][0] = *(const uint32_t*)&sBh[cb * PADK + k0 + lc * 2];
                bH[nt][1] = *(const uint32_t*)&sBh[cb * PADK + k0 + 8 + lc * 2];
                bL[nt][0] = *(const uint32_t*)&sBl[cb * PADK + k0 + lc * 2];
                bL[nt][1] = *(const uint32_t*)&sBl[cb * PADK + k0 + 8 + lc * 2];
            }
            // A hi fragments, 4 m16 tiles
            uint32_t af[4][4];
#pragma unroll
            for (int mt = 0; mt < 4; mt++) {
                int rb = wm * 64 + mt * 16 + lr;
                af[mt][0] = *(const uint32_t*)&sAh[rb * PADK + k0 + lc * 2];
                af[mt][1] = *(const uint32_t*)&sAh[(rb + 8) * PADK + k0 + lc * 2];
                af[mt][2] = *(const uint32_t*)&sAh[rb * PADK + k0 + 8 + lc * 2];
                af[mt][3] = *(const uint32_t*)&sAh[(rb + 8) * PADK + k0 + 8 + lc * 2];
            }
#pragma unroll
            for (int mt = 0; mt < 4; mt++)
#pragma unroll
                for (int nt = 0; nt < 4; nt++) {
                    mma16816(acc[mt][nt], af[mt], bH[nt]);  // Ah*Bh
                    mma16816(acc[mt][nt], af[mt], bL[nt]);  // Ah*Bl
                }
            // A lo fragments (reuse regs)
#pragma unroll
            for (int mt = 0; mt < 4; mt++) {
                int rb = wm * 64 + mt * 16 + lr;
                af[mt][0] = *(const uint32_t*)&sAl[rb * PADK + k0 + lc * 2];
                af[mt][1] = *(const uint32_t*)&sAl[(rb + 8) * PADK + k0 + lc * 2];
                af[mt][2] = *(const uint32_t*)&sAl[rb * PADK + k0 + 8 + lc * 2];
                af[mt][3] = *(const uint32_t*)&sAl[(rb + 8) * PADK + k0 + 8 + lc * 2];
            }
#pragma unroll
            for (int mt = 0; mt < 4; mt++)
#pragma unroll
                for (int nt = 0; nt < 4; nt++)
                    mma16816(acc[mt][nt], af[mt], bH[nt]);  // Al*Bh
        }
        __syncthreads();
    }

    // ---- epilogue: write head-major [B,H,L,64] with scale ----
    const float scale = (sel == 0) ? 0.125f : 1.0f;
    float* __restrict__ out = (sel == 0) ? g_q : (sel == 1) ? g_k : g_v;
#pragma unroll
    for (int mt = 0; mt < 4; mt++) {
#pragma unroll
        for (int half = 0; half < 2; half++) {
            int m = m0 + wm * 64 + mt * 16 + half * 8 + lr;
            int b = m >> 10;
            int l = m & 1023;
#pragma unroll
            for (int nt = 0; nt < 4; nt++) {
                int n = n0 + wn * 32 + nt * 8 + lc * 2;
                int h = n >> 6;
                int d = n & 63;
                float2 o;
                o.x = acc[mt][nt][half * 2 + 0] * scale;
                o.y = acc[mt][nt][half * 2 + 1] * scale;
                *(float2*)&out[(((size_t)(b * NHEAD + h) * SEQLEN) + l) * HDIM + d] = o;
            }
        }
    }
}

// ---------------------------------------------------------------------------
// Flash attention (causal), unchanged from round 1 baseline.
// ---------------------------------------------------------------------------
__global__ __launch_bounds__(128) void attn_kernel(float* __restrict__ out)
{
    const int bh  = blockIdx.y;
    const int q0  = blockIdx.x * 128;
    const int tid = threadIdx.x;
    const int qi  = q0 + tid;

    __shared__ float sK[32][64];
    __shared__ float sV[32][64];

    const float* __restrict__ Qb = g_q + (size_t)bh * SEQLEN * HDIM;
    const float* __restrict__ Kb = g_k + (size_t)bh * SEQLEN * HDIM;
    const float* __restrict__ Vb = g_v + (size_t)bh * SEQLEN * HDIM;

    float q[64];
#pragma unroll
    for (int d4 = 0; d4 < 16; d4++) {
        float4 v = *(const float4*)&Qb[qi * HDIM + d4 * 4];
        q[d4 * 4 + 0] = v.x; q[d4 * 4 + 1] = v.y;
        q[d4 * 4 + 2] = v.z; q[d4 * 4 + 3] = v.w;
    }

    float o[64];
#pragma unroll
    for (int d = 0; d < 64; d++) o[d] = 0.f;
    float mrun = -1e30f, lsum = 0.f;

    const int kend = q0 + 128;
    for (int k0 = 0; k0 < kend; k0 += 32) {
        __syncthreads();
#pragma unroll
        for (int i = 0; i < 4; i++) {
            int idx = tid + i * 128;
            int r   = idx >> 4;
            int c4  = idx & 15;
            *(float4*)&sK[r][c4 * 4] =
                *(const float4*)&Kb[(k0 + r) * HDIM + c4 * 4];
            *(float4*)&sV[r][c4 * 4] =
                *(const float4*)&Vb[(k0 + r) * HDIM + c4 * 4];
        }
        __syncthreads();

        float sc[32];
        float tmax = -1e30f;
#pragma unroll
        for (int kk = 0; kk < 32; kk++) {
            float s = 0.f;
#pragma unroll
            for (int d4 = 0; d4 < 16; d4++) {
                float4 kv = *(const float4*)&sK[kk][d4 * 4];
                s += q[d4 * 4 + 0] * kv.x + q[d4 * 4 + 1] * kv.y
                   + q[d4 * 4 + 2] * kv.z + q[d4 * 4 + 3] * kv.w;
            }
            if (k0 + kk > qi) s = -1e30f;
            sc[kk] = s;
            tmax = fmaxf(tmax, s);
        }

        float mnew = fmaxf(mrun, tmax);
        float corr = __expf(mrun - mnew);
        mrun = mnew;
        lsum *= corr;
#pragma unroll
        for (int d = 0; d < 64; d++) o[d] *= corr;

#pragma unroll
        for (int kk = 0; kk < 32; kk++) {
            float p = __expf(sc[kk] - mrun);
            lsum += p;
#pragma unroll
            for (int d4 = 0; d4 < 16; d4++) {
                float4 vv = *(const float4*)&sV[kk][d4 * 4];
                o[d4 * 4 + 0] += p * vv.x;
                o[d4 * 4 + 1] += p * vv.y;
                o[d4 * 4 + 2] += p * vv.z;
                o[d4 * 4 + 3] += p * vv.w;
            }
        }
    }

    const float inv = 1.f / lsum;
    const int b = bh >> 3;
    const int h = bh & 7;
    float* orow = out + ((size_t)(b * SEQLEN + qi) * DOUT) + h * HDIM;
#pragma unroll
    for (int d4 = 0; d4 < 16; d4++) {
        float4 v = make_float4(o[d4 * 4 + 0] * inv, o[d4 * 4 + 1] * inv,
                               o[d4 * 4 + 2] * inv, o[d4 * 4 + 3] * inv);
        *(float4*)&orow[d4 * 4] = v;
    }
}

// ---------------------------------------------------------------------------
extern "C" void kernel_launch(void* const* d_in, const int* in_sizes, int n_in,
                              void* d_out, int out_size)
{
    const float* Qs = (const float*)d_in[0];
    const float* Ks = (const float*)d_in[1];
    const float* Vs = (const float*)d_in[2];
    const float* WQ = (const float*)d_in[3];
    const float* WK = (const float*)d_in[4];
    const float* WV = (const float*)d_in[5];
    float* out = (float*)d_out;

    convert_x<<<dim3(MTOT * DIN / 4 / 256, 3), 256>>>(Qs, Ks, Vs);
    convert_wt<<<dim3(DOUT / 32, DIN / 32, 3), dim3(32, 8)>>>(WQ, WK, WV);
    proj_mma_sync<<<dim3(DOUT / 128, MTOT / 128, 3), 256>>>();

    dim3 agrid(SEQLEN / 128, BATCH * NHEAD);
    attn_kernel<<<agrid, 128>>>(out);
}

// round 5
// speedup vs baseline: 2.4610x; 2.0587x over previous
#include <cuda_runtime.h>
#include <cuda_bf16.h>
#include <cstdint>

#define BATCH 8
#define SEQLEN 1024
#define DIN 512
#define NHEAD 8
#define HDIM 64
#define DOUT 512
#define MTOT (BATCH * SEQLEN)   // 8192
#define NBH (BATCH * NHEAD)     // 64

// ---------------------------------------------------------------------------
// Static device scratch (no runtime allocation allowed)
// ---------------------------------------------------------------------------
__device__ __align__(16) float g_q[NBH * SEQLEN * HDIM];
__device__ __align__(16) float g_k[NBH * SEQLEN * HDIM];
__device__ __align__(16) float g_v[NBH * SEQLEN * HDIM];

// bf16 hi/lo splits of inputs for projections
__device__ __align__(16) __nv_bfloat16 g_xhi[3 * MTOT * DIN];
__device__ __align__(16) __nv_bfloat16 g_xlo[3 * MTOT * DIN];
__device__ __align__(16) __nv_bfloat16 g_wthi[3 * DOUT * DIN];
__device__ __align__(16) __nv_bfloat16 g_wtlo[3 * DOUT * DIN];

// bf16 hi/lo of projected q, k ([bh][l][64]) and V transposed ([bh][d][1024])
__device__ __align__(16) __nv_bfloat16 g_qhi[NBH * SEQLEN * HDIM];
__device__ __align__(16) __nv_bfloat16 g_qlo[NBH * SEQLEN * HDIM];
__device__ __align__(16) __nv_bfloat16 g_khi[NBH * SEQLEN * HDIM];
__device__ __align__(16) __nv_bfloat16 g_klo[NBH * SEQLEN * HDIM];
__device__ __align__(16) __nv_bfloat16 g_vthi[NBH * HDIM * SEQLEN];
__device__ __align__(16) __nv_bfloat16 g_vtlo[NBH * HDIM * SEQLEN];

__device__ __forceinline__ void split_bf16(float x, __nv_bfloat16& h, __nv_bfloat16& l) {
    h = __float2bfloat16(x);
    l = __float2bfloat16(x - __bfloat162float(h));
}

__device__ __forceinline__ void mma16816(float* c, const uint32_t* a, const uint32_t* b) {
    asm volatile(
        "mma.sync.aligned.m16n8k16.row.col.f32.bf16.bf16.f32 "
        "{%0,%1,%2,%3}, {%4,%5,%6,%7}, {%8,%9}, {%0,%1,%2,%3};"
        : "+f"(c[0]), "+f"(c[1]), "+f"(c[2]), "+f"(c[3])
        : "r"(a[0]), "r"(a[1]), "r"(a[2]), "r"(a[3]), "r"(b[0]), "r"(b[1]));
}

// Fast exp2 on the FMA/ALU pipes (no MUFU). t <= ~0 expected; exact 1.0 at t=0.
// max rel err ~4e-5 over f in [-0.5,0.5].
__device__ __forceinline__ float fexp2(float t) {
    t = fmaxf(t, -126.0f);
    float z = t + 12582912.0f;                 // 1.5 * 2^23: round-to-nearest-int
    int   i = __float_as_int(z) - 0x4B400000;  // integer part (signed)
    float f = t - (z - 12582912.0f);           // frac in [-0.5, 0.5]
    float p = fmaf(f, 0.00961813f, 0.05550411f);
    p = fmaf(f, p, 0.24022651f);
    p = fmaf(f, p, 0.69314718f);
    p = fmaf(f, p, 1.0f);
    return p * __int_as_float((i + 127) << 23);
}
#define L2E 1.4426950408889634f

__device__ __forceinline__ void split_pack(float x, float y, uint32_t& hi, uint32_t& lo) {
    __nv_bfloat16 hx = __float2bfloat16(x), hy = __float2bfloat16(y);
    float rx = x - __bfloat162float(hx);
    float ry = y - __bfloat162float(hy);
    __nv_bfloat162 H(hx, hy);
    __nv_bfloat162 L(__float2bfloat16(rx), __float2bfloat16(ry));
    hi = *(uint32_t*)&H;
    lo = *(uint32_t*)&L;
}

// ---------------------------------------------------------------------------
// Conversion: X (fp32) -> bf16 hi/lo
// ---------------------------------------------------------------------------
__global__ __launch_bounds__(256) void convert_x(
    const float* __restrict__ x0, const float* __restrict__ x1,
    const float* __restrict__ x2)
{
    const int sel = blockIdx.y;
    const float* __restrict__ x = (sel == 0) ? x0 : (sel == 1) ? x1 : x2;
    const int i = blockIdx.x * 256 + threadIdx.x;
    float4 v = ((const float4*)x)[i];
    __nv_bfloat16 h0, h1, h2, h3, l0, l1, l2, l3;
    split_bf16(v.x, h0, l0); split_bf16(v.y, h1, l1);
    split_bf16(v.z, h2, l2); split_bf16(v.w, h3, l3);
    const size_t e = (size_t)sel * (MTOT * DIN) + (size_t)i * 4;
    *(__nv_bfloat162*)&g_xhi[e]     = __nv_bfloat162(h0, h1);
    *(__nv_bfloat162*)&g_xhi[e + 2] = __nv_bfloat162(h2, h3);
    *(__nv_bfloat162*)&g_xlo[e]     = __nv_bfloat162(l0, l1);
    *(__nv_bfloat162*)&g_xlo[e + 2] = __nv_bfloat162(l2, l3);
}

__global__ __launch_bounds__(256) void convert_wt(
    const float* __restrict__ w0, const float* __restrict__ w1,
    const float* __restrict__ w2)
{
    const int sel = blockIdx.z;
    const float* __restrict__ W = (sel == 0) ? w0 : (sel == 1) ? w1 : w2;
    __shared__ float tile[32][33];
    const int n0 = blockIdx.x * 32, k0 = blockIdx.y * 32;
    const int tx = threadIdx.x, ty = threadIdx.y;
#pragma unroll
    for (int i = 0; i < 32; i += 8)
        tile[ty + i][tx] = W[(k0 + ty + i) * DOUT + n0 + tx];
    __syncthreads();
    const size_t base = (size_t)sel * (DOUT * DIN);
#pragma unroll
    for (int i = 0; i < 32; i += 8) {
        int n = ty + i;
        float v = tile[tx][n];
        __nv_bfloat16 h, l;
        split_bf16(v, h, l);
        g_wthi[base + (size_t)(n0 + n) * DIN + k0 + tx] = h;
        g_wtlo[base + (size_t)(n0 + n) * DIN + k0 + tx] = l;
    }
}

// ---------------------------------------------------------------------------
// Projection GEMM via mma.sync bf16-split (unchanged from round 4, passing).
// ---------------------------------------------------------------------------
#define PADK 40

__global__ __launch_bounds__(256) void proj_mma_sync()
{
    __shared__ __nv_bfloat16 sAh[128 * PADK];
    __shared__ __nv_bfloat16 sAl[128 * PADK];
    __shared__ __nv_bfloat16 sBh[128 * PADK];
    __shared__ __nv_bfloat16 sBl[128 * PADK];

    const int sel = blockIdx.z;
    const int n0  = blockIdx.x * 128;
    const int m0  = blockIdx.y * 128;
    const int tid = threadIdx.x;
    const int w   = tid >> 5;
    const int lane = tid & 31;
    const int wm = w >> 2, wn = w & 3;
    const int lr = lane >> 2, lc = lane & 3;

    const __nv_bfloat16* __restrict__ Ahp = g_xhi + (size_t)sel * (MTOT * DIN);
    const __nv_bfloat16* __restrict__ Alp = g_xlo + (size_t)sel * (MTOT * DIN);
    const __nv_bfloat16* __restrict__ Bhp = g_wthi + (size_t)sel * (DOUT * DIN);
    const __nv_bfloat16* __restrict__ Blp = g_wtlo + (size_t)sel * (DOUT * DIN);

    float acc[4][4][4];
#pragma unroll
    for (int i = 0; i < 4; i++)
#pragma unroll
        for (int j = 0; j < 4; j++)
#pragma unroll
            for (int r = 0; r < 4; r++) acc[i][j][r] = 0.f;

    for (int kk = 0; kk < DIN; kk += 32) {
#pragma unroll
        for (int i = 0; i < 2; i++) {
            int idx = tid + i * 256;
            int r = idx >> 2;
            int c = idx & 3;
            size_t ga = (size_t)(m0 + r) * DIN + kk + c * 8;
            size_t gb = (size_t)(n0 + r) * DIN + kk + c * 8;
            *(uint4*)&sAh[r * PADK + c * 8] = *(const uint4*)&Ahp[ga];
            *(uint4*)&sAl[r * PADK + c * 8] = *(const uint4*)&Alp[ga];
            *(uint4*)&sBh[r * PADK + c * 8] = *(const uint4*)&Bhp[gb];
            *(uint4*)&sBl[r * PADK + c * 8] = *(const uint4*)&Blp[gb];
        }
        __syncthreads();

#pragma unroll
        for (int ks = 0; ks < 2; ks++) {
            const int k0 = ks * 16;
            uint32_t bH[4][2], bL[4][2];
#pragma unroll
            for (int nt = 0; nt < 4; nt++) {
                int cb = wn * 32 + nt * 8 + lr;
                bH[nt][0] = *(const uint32_t*)&sBh[cb * PADK + k0 + lc * 2];
                bH[nt][1] = *(const uint32_t*)&sBh[cb * PADK + k0 + 8 + lc * 2];
                bL[nt][0] = *(const uint32_t*)&sBl[cb * PADK + k0 + lc * 2];
                bL[nt][1] = *(const uint32_t*)&sBl[cb * PADK + k0 + 8 + lc * 2];
            }
            uint32_t af[4][4];
#pragma unroll
            for (int mt = 0; mt < 4; mt++) {
                int rb = wm * 64 + mt * 16 + lr;
                af[mt][0] = *(const uint32_t*)&sAh[rb * PADK + k0 + lc * 2];
                af[mt][1] = *(const uint32_t*)&sAh[(rb + 8) * PADK + k0 + lc * 2];
                af[mt][2] = *(const uint32_t*)&sAh[rb * PADK + k0 + 8 + lc * 2];
                af[mt][3] = *(const uint32_t*)&sAh[(rb + 8) * PADK + k0 + 8 + lc * 2];
            }
#pragma unroll
            for (int mt = 0; mt < 4; mt++)
#pragma unroll
                for (int nt = 0; nt < 4; nt++) {
                    mma16816(acc[mt][nt], af[mt], bH[nt]);
                    mma16816(acc[mt][nt], af[mt], bL[nt]);
                }
#pragma unroll
            for (int mt = 0; mt < 4; mt++) {
                int rb = wm * 64 + mt * 16 + lr;
                af[mt][0] = *(const uint32_t*)&sAl[rb * PADK + k0 + lc * 2];
                af[mt][1] = *(const uint32_t*)&sAl[(rb + 8) * PADK + k0 + lc * 2];
                af[mt][2] = *(const uint32_t*)&sAl[rb * PADK + k0 + 8 + lc * 2];
                af[mt][3] = *(const uint32_t*)&sAl[(rb + 8) * PADK + k0 + 8 + lc * 2];
            }
#pragma unroll
            for (int mt = 0; mt < 4; mt++)
#pragma unroll
                for (int nt = 0; nt < 4; nt++)
                    mma16816(acc[mt][nt], af[mt], bH[nt]);
        }
        __syncthreads();
    }

    const float scale = (sel == 0) ? 0.125f : 1.0f;
    float* __restrict__ out = (sel == 0) ? g_q : (sel == 1) ? g_k : g_v;
#pragma unroll
    for (int mt = 0; mt < 4; mt++) {
#pragma unroll
        for (int half = 0; half < 2; half++) {
            int m = m0 + wm * 64 + mt * 16 + half * 8 + lr;
            int b = m >> 10;
            int l = m & 1023;
#pragma unroll
            for (int nt = 0; nt < 4; nt++) {
                int n = n0 + wn * 32 + nt * 8 + lc * 2;
                int h = n >> 6;
                int d = n & 63;
                float2 o;
                o.x = acc[mt][nt][half * 2 + 0] * scale;
                o.y = acc[mt][nt][half * 2 + 1] * scale;
                *(float2*)&out[(((size_t)(b * NHEAD + h) * SEQLEN) + l) * HDIM + d] = o;
            }
        }
    }
}

// ---------------------------------------------------------------------------
// Prep: q,k fp32 -> bf16 hi/lo (elementwise)
// ---------------------------------------------------------------------------
__global__ __launch_bounds__(256) void convert_qk()
{
    const int sel = blockIdx.y;   // 0 = q, 1 = k
    const float* __restrict__ src = sel ? g_k : g_q;
    __nv_bfloat16* __restrict__ dh = sel ? g_khi : g_qhi;
    __nv_bfloat16* __restrict__ dl = sel ? g_klo : g_qlo;
    const int i = blockIdx.x * 256 + threadIdx.x;
    float4 v = ((const float4*)src)[i];
    __nv_bfloat16 h0, h1, h2, h3, l0, l1, l2, l3;
    split_bf16(v.x, h0, l0); split_bf16(v.y, h1, l1);
    split_bf16(v.z, h2, l2); split_bf16(v.w, h3, l3);
    const size_t e = (size_t)i * 4;
    *(__nv_bfloat162*)&dh[e]     = __nv_bfloat162(h0, h1);
    *(__nv_bfloat162*)&dh[e + 2] = __nv_bfloat162(h2, h3);
    *(__nv_bfloat162*)&dl[e]     = __nv_bfloat162(l0, l1);
    *(__nv_bfloat162*)&dl[e + 2] = __nv_bfloat162(l2, l3);
}

// ---------------------------------------------------------------------------
// Prep: V fp32 [bh][l][64] -> transposed bf16 hi/lo [bh][d][1024]
// ---------------------------------------------------------------------------
__global__ __launch_bounds__(256) void transpose_v()
{
    const int bh = blockIdx.z;
    const int l0 = blockIdx.x * 32;
    const int d0 = blockIdx.y * 32;
    __shared__ float tile[32][33];
    const int tx = threadIdx.x, ty = threadIdx.y;   // (32, 8)
    const float* __restrict__ src = g_v + (size_t)bh * SEQLEN * HDIM;
#pragma unroll
    for (int i = 0; i < 32; i += 8)
        tile[ty + i][tx] = src[(l0 + ty + i) * HDIM + d0 + tx];
    __syncthreads();
    const size_t base = (size_t)bh * (HDIM * SEQLEN);
#pragma unroll
    for (int i = 0; i < 32; i += 8) {
        int d = ty + i;
        float v = tile[tx][d];                  // = V[l0+tx][d0+d]
        __nv_bfloat16 h, l;
        split_bf16(v, h, l);
        g_vthi[base + (size_t)(d0 + d) * SEQLEN + l0 + tx] = h;
        g_vtlo[base + (size_t)(d0 + d) * SEQLEN + l0 + tx] = l;
    }
}

// ---------------------------------------------------------------------------
// Flash attention on tensor cores (bf16-split mma.sync) + FMA-pipe exp.
// Block: 128 q rows of one (b,h); 8 warps x 16 rows; key tiles of 64.
// ---------------------------------------------------------------------------
#define AP 72   // smem row stride (bf16) for 64-wide tiles: conflict-free frags

__global__ __launch_bounds__(256) void attn_mma(float* __restrict__ out)
{
    const int bh  = blockIdx.y;
    const int q0  = blockIdx.x * 128;
    const int tid = threadIdx.x;
    const int w    = tid >> 5;
    const int lane = tid & 31;
    const int lr = lane >> 2, lc = lane & 3;
    const int wr0 = q0 + w * 16;            // first q row of this warp (local l)

    __shared__ __align__(16) __nv_bfloat16 sKh[64 * AP];
    __shared__ __align__(16) __nv_bfloat16 sKl[64 * AP];
    __shared__ __align__(16) __nv_bfloat16 sVh[64 * AP];  // [d][key]
    __shared__ __align__(16) __nv_bfloat16 sVl[64 * AP];

    const size_t bhoff = (size_t)bh * (SEQLEN * HDIM);
    const __nv_bfloat16* __restrict__ Kh = g_khi + bhoff;
    const __nv_bfloat16* __restrict__ Kl = g_klo + bhoff;
    const __nv_bfloat16* __restrict__ Vh = g_vthi + bhoff;  // [d][1024]
    const __nv_bfloat16* __restrict__ Vl = g_vtlo + bhoff;

    // Q fragments resident in registers: 4 k16 steps x 4 regs, hi and lo.
    uint32_t aQh[4][4], aQl[4][4];
    {
        const __nv_bfloat16* __restrict__ Qh = g_qhi + bhoff;
        const __nv_bfloat16* __restrict__ Ql = g_qlo + bhoff;
#pragma unroll
        for (int ks = 0; ks < 4; ks++) {
            int k = ks * 16 + 2 * lc;
            aQh[ks][0] = *(const uint32_t*)&Qh[(wr0 + lr) * HDIM + k];
            aQh[ks][1] = *(const uint32_t*)&Qh[(wr0 + 8 + lr) * HDIM + k];
            aQh[ks][2] = *(const uint32_t*)&Qh[(wr0 + lr) * HDIM + k + 8];
            aQh[ks][3] = *(const uint32_t*)&Qh[(wr0 + 8 + lr) * HDIM + k + 8];
            aQl[ks][0] = *(const uint32_t*)&Ql[(wr0 + lr) * HDIM + k];
            aQl[ks][1] = *(const uint32_t*)&Ql[(wr0 + 8 + lr) * HDIM + k];
            aQl[ks][2] = *(const uint32_t*)&Ql[(wr0 + lr) * HDIM + k + 8];
            aQl[ks][3] = *(const uint32_t*)&Ql[(wr0 + 8 + lr) * HDIM + k + 8];
        }
    }

    float o[8][4];
#pragma unroll
    for (int nt = 0; nt < 8; nt++)
#pragma unroll
        for (int j = 0; j < 4; j++) o[nt][j] = 0.f;
    float m0 = -1e30f, m1 = -1e30f, l0 = 0.f, l1 = 0.f;

    const int kend = q0 + 128;
    for (int k0 = 0; k0 < kend; k0 += 64) {
        // ---- stage K hi/lo and V^T hi/lo tiles (all threads) ----
#pragma unroll
        for (int i = 0; i < 2; i++) {
            int idx = tid + i * 256;          // 0..511
            int r = idx >> 3;                 // 0..63
            int c = idx & 7;                  // 16B chunk
            *(uint4*)&sKh[r * AP + c * 8] = *(const uint4*)&Kh[(k0 + r) * HDIM + c * 8];
            *(uint4*)&sKl[r * AP + c * 8] = *(const uint4*)&Kl[(k0 + r) * HDIM + c * 8];
            *(uint4*)&sVh[r * AP + c * 8] = *(const uint4*)&Vh[(size_t)r * SEQLEN + k0 + c * 8];
            *(uint4*)&sVl[r * AP + c * 8] = *(const uint4*)&Vl[(size_t)r * SEQLEN + k0 + c * 8];
        }
        __syncthreads();

        if (k0 <= wr0 + 15) {   // warp-uniform: tile not fully above diagonal
            // ---- S = Q K^T (3-pass split) ----
            float s[8][4];
#pragma unroll
            for (int nt = 0; nt < 8; nt++)
#pragma unroll
                for (int j = 0; j < 4; j++) s[nt][j] = 0.f;

#pragma unroll
            for (int nt = 0; nt < 8; nt++) {
                const int cb = (nt * 8 + lr) * AP;
#pragma unroll
                for (int ks = 0; ks < 4; ks++) {
                    uint32_t bKh[2], bKl[2];
                    bKh[0] = *(const uint32_t*)&sKh[cb + ks * 16 + 2 * lc];
                    bKh[1] = *(const uint32_t*)&sKh[cb + ks * 16 + 8 + 2 * lc];
                    bKl[0] = *(const uint32_t*)&sKl[cb + ks * 16 + 2 * lc];
                    bKl[1] = *(const uint32_t*)&sKl[cb + ks * 16 + 8 + 2 * lc];
                    mma16816(s[nt], aQh[ks], bKh);
                    mma16816(s[nt], aQh[ks], bKl);
                    mma16816(s[nt], aQl[ks], bKh);
                }
            }

            // ---- causal mask (only for diagonal-straddling tiles) ----
            if (k0 + 63 > wr0) {
                const int row0 = wr0 + lr, row1 = wr0 + 8 + lr;
#pragma unroll
                for (int nt = 0; nt < 8; nt++) {
                    int kc = k0 + nt * 8 + 2 * lc;
                    if (kc > row0)     s[nt][0] = -1e30f;
                    if (kc + 1 > row0) s[nt][1] = -1e30f;
                    if (kc > row1)     s[nt][2] = -1e30f;
                    if (kc + 1 > row1) s[nt][3] = -1e30f;
                }
            }

            // ---- online softmax ----
            float tm0 = -1e30f, tm1 = -1e30f;
#pragma unroll
            for (int nt = 0; nt < 8; nt++) {
                tm0 = fmaxf(tm0, fmaxf(s[nt][0], s[nt][1]));
                tm1 = fmaxf(tm1, fmaxf(s[nt][2], s[nt][3]));
            }
            tm0 = fmaxf(tm0, __shfl_xor_sync(0xffffffff, tm0, 1));
            tm0 = fmaxf(tm0, __shfl_xor_sync(0xffffffff, tm0, 2));
            tm1 = fmaxf(tm1, __shfl_xor_sync(0xffffffff, tm1, 1));
            tm1 = fmaxf(tm1, __shfl_xor_sync(0xffffffff, tm1, 2));

            float mn0 = fmaxf(m0, tm0), mn1 = fmaxf(m1, tm1);
            float cr0 = fexp2((m0 - mn0) * L2E);
            float cr1 = fexp2((m1 - mn1) * L2E);
            m0 = mn0; m1 = mn1;
            const float nm0 = -m0 * L2E, nm1 = -m1 * L2E;

            float ls0 = 0.f, ls1 = 0.f;
#pragma unroll
            for (int nt = 0; nt < 8; nt++) {
                s[nt][0] = fexp2(fmaf(s[nt][0], L2E, nm0));
                s[nt][1] = fexp2(fmaf(s[nt][1], L2E, nm0));
                s[nt][2] = fexp2(fmaf(s[nt][2], L2E, nm1));
                s[nt][3] = fexp2(fmaf(s[nt][3], L2E, nm1));
                ls0 += s[nt][0] + s[nt][1];
                ls1 += s[nt][2] + s[nt][3];
            }
            ls0 += __shfl_xor_sync(0xffffffff, ls0, 1);
            ls0 += __shfl_xor_sync(0xffffffff, ls0, 2);
            ls1 += __shfl_xor_sync(0xffffffff, ls1, 1);
            ls1 += __shfl_xor_sync(0xffffffff, ls1, 2);
            l0 = l0 * cr0 + ls0;
            l1 = l1 * cr1 + ls1;
#pragma unroll
            for (int nt = 0; nt < 8; nt++) {
                o[nt][0] *= cr0; o[nt][1] *= cr0;
                o[nt][2] *= cr1; o[nt][3] *= cr1;
            }

            // ---- P fragments from S registers (C-layout == A-layout pairs) ----
            uint32_t pH[4][4], pL[4][4];
#pragma unroll
            for (int ks = 0; ks < 4; ks++) {
                split_pack(s[2*ks][0],   s[2*ks][1],   pH[ks][0], pL[ks][0]);
                split_pack(s[2*ks][2],   s[2*ks][3],   pH[ks][1], pL[ks][1]);
                split_pack(s[2*ks+1][0], s[2*ks+1][1], pH[ks][2], pL[ks][2]);
                split_pack(s[2*ks+1][2], s[2*ks+1][3], pH[ks][3], pL[ks][3]);
            }

            // ---- O += P V (3-pass split) ----
#pragma unroll
            for (int dt = 0; dt < 8; dt++) {
                const int cb = (dt * 8 + lr) * AP;
#pragma unroll
                for (int ks = 0; ks < 4; ks++) {
                    uint32_t bVh[2], bVl[2];
                    bVh[0] = *(const uint32_t*)&sVh[cb + ks * 16 + 2 * lc];
                    bVh[1] = *(const uint32_t*)&sVh[cb + ks * 16 + 8 + 2 * lc];
                    bVl[0] = *(const uint32_t*)&sVl[cb + ks * 16 + 2 * lc];
                    bVl[1] = *(const uint32_t*)&sVl[cb + ks * 16 + 8 + 2 * lc];
                    mma16816(o[dt], pH[ks], bVh);
                    mma16816(o[dt], pH[ks], bVl);
                    mma16816(o[dt], pL[ks], bVh);
                }
            }
        }
        __syncthreads();
    }

    // ---- epilogue ----
    const float i0 = 1.f / l0, i1 = 1.f / l1;
    const int b = bh >> 3;
    const int h = bh & 7;
    const int row0 = wr0 + lr, row1 = wr0 + 8 + lr;
    float* __restrict__ o0 = out + ((size_t)(b * SEQLEN + row0) * DOUT) + h * HDIM;
    float* __restrict__ o1 = out + ((size_t)(b * SEQLEN + row1) * DOUT) + h * HDIM;
#pragma unroll
    for (int nt = 0; nt < 8; nt++) {
        int d = nt * 8 + 2 * lc;
        *(float2*)&o0[d] = make_float2(o[nt][0] * i0, o[nt][1] * i0);
        *(float2*)&o1[d] = make_float2(o[nt][2] * i1, o[nt][3] * i1);
    }
}

// ---------------------------------------------------------------------------
extern "C" void kernel_launch(void* const* d_in, const int* in_sizes, int n_in,
                              void* d_out, int out_size)
{
    const float* Qs = (const float*)d_in[0];
    const float* Ks = (const float*)d_in[1];
    const float* Vs = (const float*)d_in[2];
    const float* WQ = (const float*)d_in[3];
    const float* WK = (const float*)d_in[4];
    const float* WV = (const float*)d_in[5];
    float* out = (float*)d_out;

    convert_x<<<dim3(MTOT * DIN / 4 / 256, 3), 256>>>(Qs, Ks, Vs);
    convert_wt<<<dim3(DOUT / 32, DIN / 32, 3), dim3(32, 8)>>>(WQ, WK, WV);
    proj_mma_sync<<<dim3(DOUT / 128, MTOT / 128, 3), 256>>>();

    convert_qk<<<dim3(NBH * SEQLEN * HDIM / 4 / 256, 2), 256>>>();
    transpose_v<<<dim3(SEQLEN / 32, HDIM / 32, NBH), dim3(32, 8)>>>();

    attn_mma<<<dim3(SEQLEN / 128, NBH), 256>>>(out);
}

// round 7
// speedup vs baseline: 2.8291x; 1.1496x over previous
#include <cuda_runtime.h>
#include <cuda_bf16.h>
#include <cstdint>

#define BATCH 8
#define SEQLEN 1024
#define DIN 512
#define NHEAD 8
#define HDIM 64
#define DOUT 512
#define MTOT (BATCH * SEQLEN)   // 8192
#define NBH (BATCH * NHEAD)     // 64

// ---------------------------------------------------------------------------
// Static device scratch (no runtime allocation allowed)
// ---------------------------------------------------------------------------
__device__ __align__(16) float g_v[NBH * SEQLEN * HDIM];

__device__ __align__(16) __nv_bfloat16 g_xhi[3 * MTOT * DIN];
__device__ __align__(16) __nv_bfloat16 g_xlo[3 * MTOT * DIN];
__device__ __align__(16) __nv_bfloat16 g_wthi[3 * DOUT * DIN];
__device__ __align__(16) __nv_bfloat16 g_wtlo[3 * DOUT * DIN];

__device__ __align__(16) __nv_bfloat16 g_qhi[NBH * SEQLEN * HDIM];
__device__ __align__(16) __nv_bfloat16 g_qlo[NBH * SEQLEN * HDIM];
__device__ __align__(16) __nv_bfloat16 g_khi[NBH * SEQLEN * HDIM];
__device__ __align__(16) __nv_bfloat16 g_klo[NBH * SEQLEN * HDIM];
__device__ __align__(16) __nv_bfloat16 g_vthi[NBH * HDIM * SEQLEN];
__device__ __align__(16) __nv_bfloat16 g_vtlo[NBH * HDIM * SEQLEN];

__device__ __forceinline__ void split_bf16(float x, __nv_bfloat16& h, __nv_bfloat16& l) {
    h = __float2bfloat16(x);
    l = __float2bfloat16(x - __bfloat162float(h));
}

__device__ __forceinline__ void mma16816(float* c, const uint32_t* a, const uint32_t* b) {
    asm volatile(
        "mma.sync.aligned.m16n8k16.row.col.f32.bf16.bf16.f32 "
        "{%0,%1,%2,%3}, {%4,%5,%6,%7}, {%8,%9}, {%0,%1,%2,%3};"
        : "+f"(c[0]), "+f"(c[1]), "+f"(c[2]), "+f"(c[3])
        : "r"(a[0]), "r"(a[1]), "r"(a[2]), "r"(a[3]), "r"(b[0]), "r"(b[1]));
}

// 16B global->shared async copy (sm_80 path, base-target safe)
__device__ __forceinline__ void cp16(void* smem_dst, const void* gsrc) {
    uint32_t sa = (uint32_t)__cvta_generic_to_shared(smem_dst);
    asm volatile("cp.async.cg.shared.global [%0], [%1], 16;" :: "r"(sa), "l"(gsrc));
}
#define CP_COMMIT() asm volatile("cp.async.commit_group;" ::: "memory")
#define CP_WAIT1()  asm volatile("cp.async.wait_group 1;" ::: "memory")
#define CP_WAIT0()  asm volatile("cp.async.wait_group 0;" ::: "memory")

// FMA-pipe exp2 (no MUFU), max rel err ~4e-5
__device__ __forceinline__ float fexp2(float t) {
    t = fmaxf(t, -126.0f);
    float z = t + 12582912.0f;
    int   i = __float_as_int(z) - 0x4B400000;
    float f = t - (z - 12582912.0f);
    float p = fmaf(f, 0.00961813f, 0.05550411f);
    p = fmaf(f, p, 0.24022651f);
    p = fmaf(f, p, 0.69314718f);
    p = fmaf(f, p, 1.0f);
    return p * __int_as_float((i + 127) << 23);
}
#define L2E 1.4426950408889634f

__device__ __forceinline__ void split_pack(float x, float y, uint32_t& hi, uint32_t& lo) {
    __nv_bfloat16 hx = __float2bfloat16(x), hy = __float2bfloat16(y);
    float rx = x - __bfloat162float(hx);
    float ry = y - __bfloat162float(hy);
    __nv_bfloat162 H(hx, hy);
    __nv_bfloat162 L(__float2bfloat16(rx), __float2bfloat16(ry));
    hi = *(uint32_t*)&H;
    lo = *(uint32_t*)&L;
}

// ---------------------------------------------------------------------------
// Conversion: X (fp32) -> bf16 hi/lo
// ---------------------------------------------------------------------------
__global__ __launch_bounds__(256) void convert_x(
    const float* __restrict__ x0, const float* __restrict__ x1,
    const float* __restrict__ x2)
{
    const int sel = blockIdx.y;
    const float* __restrict__ x = (sel == 0) ? x0 : (sel == 1) ? x1 : x2;
    const int i = blockIdx.x * 256 + threadIdx.x;
    float4 v = ((const float4*)x)[i];
    __nv_bfloat16 h0, h1, h2, h3, l0, l1, l2, l3;
    split_bf16(v.x, h0, l0); split_bf16(v.y, h1, l1);
    split_bf16(v.z, h2, l2); split_bf16(v.w, h3, l3);
    const size_t e = (size_t)sel * (MTOT * DIN) + (size_t)i * 4;
    *(__nv_bfloat162*)&g_xhi[e]     = __nv_bfloat162(h0, h1);
    *(__nv_bfloat162*)&g_xhi[e + 2] = __nv_bfloat162(h2, h3);
    *(__nv_bfloat162*)&g_xlo[e]     = __nv_bfloat162(l0, l1);
    *(__nv_bfloat162*)&g_xlo[e + 2] = __nv_bfloat162(l2, l3);
}

__global__ __launch_bounds__(256) void convert_wt(
    const float* __restrict__ w0, const float* __restrict__ w1,
    const float* __restrict__ w2)
{
    const int sel = blockIdx.z;
    const float* __restrict__ W = (sel == 0) ? w0 : (sel == 1) ? w1 : w2;
    __shared__ float tile[32][33];
    const int n0 = blockIdx.x * 32, k0 = blockIdx.y * 32;
    const int tx = threadIdx.x, ty = threadIdx.y;
#pragma unroll
    for (int i = 0; i < 32; i += 8)
        tile[ty + i][tx] = W[(k0 + ty + i) * DOUT + n0 + tx];
    __syncthreads();
    const size_t base = (size_t)sel * (DOUT * DIN);
#pragma unroll
    for (int i = 0; i < 32; i += 8) {
        int n = ty + i;
        float v = tile[tx][n];
        __nv_bfloat16 h, l;
        split_bf16(v, h, l);
        g_wthi[base + (size_t)(n0 + n) * DIN + k0 + tx] = h;
        g_wtlo[base + (size_t)(n0 + n) * DIN + k0 + tx] = l;
    }
}

// ---------------------------------------------------------------------------
// Projection GEMM, bf16-split mma.sync, 2-stage cp.async double buffer.
// Epilogue: q,k written directly as bf16 hi/lo; v written fp32 for transpose.
// ---------------------------------------------------------------------------
#define PADK 40
#define PTILE (128 * PADK)                 // bf16 elements per smem tile
#define PBUF  (4 * PTILE)                  // elements per pipeline buffer
#define PROJ_DSMEM (2 * PBUF * 2)          // bytes (81920)

__global__ __launch_bounds__(256) void proj_mma_sync()
{
    extern __shared__ __align__(16) __nv_bfloat16 dsm[];

    const int sel = blockIdx.z;
    const int n0  = blockIdx.x * 128;
    const int m0  = blockIdx.y * 128;
    const int tid = threadIdx.x;
    const int w   = tid >> 5;
    const int lane = tid & 31;
    const int wm = w >> 2, wn = w & 3;
    const int lr = lane >> 2, lc = lane & 3;

    const __nv_bfloat16* __restrict__ Ahp = g_xhi + (size_t)sel * (MTOT * DIN);
    const __nv_bfloat16* __restrict__ Alp = g_xlo + (size_t)sel * (MTOT * DIN);
    const __nv_bfloat16* __restrict__ Bhp = g_wthi + (size_t)sel * (DOUT * DIN);
    const __nv_bfloat16* __restrict__ Blp = g_wtlo + (size_t)sel * (DOUT * DIN);

    // staging indices (constant per thread)
    const int r0 = tid >> 2, c0 = (tid & 3) * 8;          // chunk 0
    const int r1 = (tid + 256) >> 2, c1 = ((tid + 256) & 3) * 8;

    auto issue = [&](int slab, int buf) {
        const int kk = slab * 32;
        __nv_bfloat16* base = dsm + buf * PBUF;
        const size_t ga0 = (size_t)(m0 + r0) * DIN + kk + c0;
        const size_t gb0 = (size_t)(n0 + r0) * DIN + kk + c0;
        const size_t ga1 = (size_t)(m0 + r1) * DIN + kk + c1;
        const size_t gb1 = (size_t)(n0 + r1) * DIN + kk + c1;
        cp16(base + 0 * PTILE + r0 * PADK + c0, Ahp + ga0);
        cp16(base + 1 * PTILE + r0 * PADK + c0, Alp + ga0);
        cp16(base + 2 * PTILE + r0 * PADK + c0, Bhp + gb0);
        cp16(base + 3 * PTILE + r0 * PADK + c0, Blp + gb0);
        cp16(base + 0 * PTILE + r1 * PADK + c1, Ahp + ga1);
        cp16(base + 1 * PTILE + r1 * PADK + c1, Alp + ga1);
        cp16(base + 2 * PTILE + r1 * PADK + c1, Bhp + gb1);
        cp16(base + 3 * PTILE + r1 * PADK + c1, Blp + gb1);
        CP_COMMIT();
    };

    float acc[4][4][4];
#pragma unroll
    for (int i = 0; i < 4; i++)
#pragma unroll
        for (int j = 0; j < 4; j++)
#pragma unroll
            for (int r = 0; r < 4; r++) acc[i][j][r] = 0.f;

    issue(0, 0);

    for (int s = 0; s < DIN / 32; s++) {
        if (s + 1 < DIN / 32) { issue(s + 1, (s + 1) & 1); CP_WAIT1(); }
        else                  { CP_WAIT0(); }
        __syncthreads();

        const __nv_bfloat16* sAh = dsm + (s & 1) * PBUF + 0 * PTILE;
        const __nv_bfloat16* sAl = dsm + (s & 1) * PBUF + 1 * PTILE;
        const __nv_bfloat16* sBh = dsm + (s & 1) * PBUF + 2 * PTILE;
        const __nv_bfloat16* sBl = dsm + (s & 1) * PBUF + 3 * PTILE;

#pragma unroll
        for (int ks = 0; ks < 2; ks++) {
            const int k0 = ks * 16;
            uint32_t bH[4][2], bL[4][2];
#pragma unroll
            for (int nt = 0; nt < 4; nt++) {
                int cb = wn * 32 + nt * 8 + lr;
                bH[nt][0] = *(const uint32_t*)&sBh[cb * PADK + k0 + lc * 2];
                bH[nt][1] = *(const uint32_t*)&sBh[cb * PADK + k0 + 8 + lc * 2];
                bL[nt][0] = *(const uint32_t*)&sBl[cb * PADK + k0 + lc * 2];
                bL[nt][1] = *(const uint32_t*)&sBl[cb * PADK + k0 + 8 + lc * 2];
            }
            uint32_t af[4][4];
#pragma unroll
            for (int mt = 0; mt < 4; mt++) {
                int rb = wm * 64 + mt * 16 + lr;
                af[mt][0] = *(const uint32_t*)&sAh[rb * PADK + k0 + lc * 2];
                af[mt][1] = *(const uint32_t*)&sAh[(rb + 8) * PADK + k0 + lc * 2];
                af[mt][2] = *(const uint32_t*)&sAh[rb * PADK + k0 + 8 + lc * 2];
                af[mt][3] = *(const uint32_t*)&sAh[(rb + 8) * PADK + k0 + 8 + lc * 2];
            }
#pragma unroll
            for (int mt = 0; mt < 4; mt++)
#pragma unroll
                for (int nt = 0; nt < 4; nt++) {
                    mma16816(acc[mt][nt], af[mt], bH[nt]);
                    mma16816(acc[mt][nt], af[mt], bL[nt]);
                }
#pragma unroll
            for (int mt = 0; mt < 4; mt++) {
                int rb = wm * 64 + mt * 16 + lr;
                af[mt][0] = *(const uint32_t*)&sAl[rb * PADK + k0 + lc * 2];
                af[mt][1] = *(const uint32_t*)&sAl[(rb + 8) * PADK + k0 + lc * 2];
                af[mt][2] = *(const uint32_t*)&sAl[rb * PADK + k0 + 8 + lc * 2];
                af[mt][3] = *(const uint32_t*)&sAl[(rb + 8) * PADK + k0 + 8 + lc * 2];
            }
#pragma unroll
            for (int mt = 0; mt < 4; mt++)
#pragma unroll
                for (int nt = 0; nt < 4; nt++)
                    mma16816(acc[mt][nt], af[mt], bH[nt]);
        }
        __syncthreads();
    }

    // ---- epilogue ----
    if (sel < 2) {
        const float scale = (sel == 0) ? 0.125f : 1.0f;
        __nv_bfloat16* __restrict__ dh = (sel == 0) ? g_qhi : g_khi;
        __nv_bfloat16* __restrict__ dl = (sel == 0) ? g_qlo : g_klo;
#pragma unroll
        for (int mt = 0; mt < 4; mt++) {
#pragma unroll
            for (int half = 0; half < 2; half++) {
                int m = m0 + wm * 64 + mt * 16 + half * 8 + lr;
                int b = m >> 10;
                int l = m & 1023;
#pragma unroll
                for (int nt = 0; nt < 4; nt++) {
                    int n = n0 + wn * 32 + nt * 8 + lc * 2;
                    int h = n >> 6;
                    int d = n & 63;
                    uint32_t hi, lo;
                    split_pack(acc[mt][nt][half * 2 + 0] * scale,
                               acc[mt][nt][half * 2 + 1] * scale, hi, lo);
                    size_t off = (((size_t)(b * NHEAD + h) * SEQLEN) + l) * HDIM + d;
                    *(uint32_t*)&dh[off] = hi;
                    *(uint32_t*)&dl[off] = lo;
                }
            }
        }
    } else {
#pragma unroll
        for (int mt = 0; mt < 4; mt++) {
#pragma unroll
            for (int half = 0; half < 2; half++) {
                int m = m0 + wm * 64 + mt * 16 + half * 8 + lr;
                int b = m >> 10;
                int l = m & 1023;
#pragma unroll
                for (int nt = 0; nt < 4; nt++) {
                    int n = n0 + wn * 32 + nt * 8 + lc * 2;
                    int h = n >> 6;
                    int d = n & 63;
                    float2 o = make_float2(acc[mt][nt][half * 2 + 0],
                                           acc[mt][nt][half * 2 + 1]);
                    *(float2*)&g_v[(((size_t)(b * NHEAD + h) * SEQLEN) + l) * HDIM + d] = o;
                }
            }
        }
    }
}

// ---------------------------------------------------------------------------
// Prep: V fp32 [bh][l][64] -> transposed bf16 hi/lo [bh][d][1024]
// ---------------------------------------------------------------------------
__global__ __launch_bounds__(256) void transpose_v()
{
    const int bh = blockIdx.z;
    const int l0 = blockIdx.x * 32;
    const int d0 = blockIdx.y * 32;
    __shared__ float tile[32][33];
    const int tx = threadIdx.x, ty = threadIdx.y;
    const float* __restrict__ src = g_v + (size_t)bh * SEQLEN * HDIM;
#pragma unroll
    for (int i = 0; i < 32; i += 8)
        tile[ty + i][tx] = src[(l0 + ty + i) * HDIM + d0 + tx];
    __syncthreads();
    const size_t base = (size_t)bh * (HDIM * SEQLEN);
#pragma unroll
    for (int i = 0; i < 32; i += 8) {
        int d = ty + i;
        float v = tile[tx][d];
        __nv_bfloat16 h, l;
        split_bf16(v, h, l);
        g_vthi[base + (size_t)(d0 + d) * SEQLEN + l0 + tx] = h;
        g_vtlo[base + (size_t)(d0 + d) * SEQLEN + l0 + tx] = l;
    }
}

// ---------------------------------------------------------------------------
// Flash attention on tensor cores, 2-stage cp.async double buffer.
// ---------------------------------------------------------------------------
#define AP 72
#define ATILE (64 * AP)                    // bf16 elements per smem tile
#define ABUF  (4 * ATILE)
#define ATTN_DSMEM (2 * ABUF * 2)          // bytes (73728)

__global__ __launch_bounds__(256) void attn_mma(float* __restrict__ out)
{
    extern __shared__ __align__(16) __nv_bfloat16 adsm[];

    const int bh  = blockIdx.y;
    const int q0  = blockIdx.x * 128;
    const int tid = threadIdx.x;
    const int w    = tid >> 5;
    const int lane = tid & 31;
    const int lr = lane >> 2, lc = lane & 3;
    const int wr0 = q0 + w * 16;

    const size_t bhoff = (size_t)bh * (SEQLEN * HDIM);
    const __nv_bfloat16* __restrict__ Kh = g_khi + bhoff;
    const __nv_bfloat16* __restrict__ Kl = g_klo + bhoff;
    const __nv_bfloat16* __restrict__ Vh = g_vthi + bhoff;
    const __nv_bfloat16* __restrict__ Vl = g_vtlo + bhoff;

    const int r0 = tid >> 3, c0 = (tid & 7) * 8;
    const int r1 = (tid + 256) >> 3, c1 = ((tid + 256) & 7) * 8;

    auto issue = [&](int tileidx, int buf) {
        const int k0 = tileidx * 64;
        __nv_bfloat16* base = adsm + buf * ABUF;
        cp16(base + 0 * ATILE + r0 * AP + c0, Kh + (size_t)(k0 + r0) * HDIM + c0);
        cp16(base + 1 * ATILE + r0 * AP + c0, Kl + (size_t)(k0 + r0) * HDIM + c0);
        cp16(base + 2 * ATILE + r0 * AP + c0, Vh + (size_t)r0 * SEQLEN + k0 + c0);
        cp16(base + 3 * ATILE + r0 * AP + c0, Vl + (size_t)r0 * SEQLEN + k0 + c0);
        cp16(base + 0 * ATILE + r1 * AP + c1, Kh + (size_t)(k0 + r1) * HDIM + c1);
        cp16(base + 1 * ATILE + r1 * AP + c1, Kl + (size_t)(k0 + r1) * HDIM + c1);
        cp16(base + 2 * ATILE + r1 * AP + c1, Vh + (size_t)r1 * SEQLEN + k0 + c1);
        cp16(base + 3 * ATILE + r1 * AP + c1, Vl + (size_t)r1 * SEQLEN + k0 + c1);
        CP_COMMIT();
    };

    // Q fragments resident in registers
    uint32_t aQh[4][4], aQl[4][4];
    {
        const __nv_bfloat16* __restrict__ Qh = g_qhi + bhoff;
        const __nv_bfloat16* __restrict__ Ql = g_qlo + bhoff;
#pragma unroll
        for (int ks = 0; ks < 4; ks++) {
            int k = ks * 16 + 2 * lc;
            aQh[ks][0] = *(const uint32_t*)&Qh[(wr0 + lr) * HDIM + k];
            aQh[ks][1] = *(const uint32_t*)&Qh[(wr0 + 8 + lr) * HDIM + k];
            aQh[ks][2] = *(const uint32_t*)&Qh[(wr0 + lr) * HDIM + k + 8];
            aQh[ks][3] = *(const uint32_t*)&Qh[(wr0 + 8 + lr) * HDIM + k + 8];
            aQl[ks][0] = *(const uint32_t*)&Ql[(wr0 + lr) * HDIM + k];
            aQl[ks][1] = *(const uint32_t*)&Ql[(wr0 + 8 + lr) * HDIM + k];
            aQl[ks][2] = *(const uint32_t*)&Ql[(wr0 + lr) * HDIM + k + 8];
            aQl[ks][3] = *(const uint32_t*)&Ql[(wr0 + 8 + lr) * HDIM + k + 8];
        }
    }

    float o[8][4];
#pragma unroll
    for (int nt = 0; nt < 8; nt++)
#pragma unroll
        for (int j = 0; j < 4; j++) o[nt][j] = 0.f;
    float m0 = -1e30f, m1 = -1e30f, l0 = 0.f, l1 = 0.f;

    const int ntiles = (q0 + 128) / 64;
    issue(0, 0);

    for (int t = 0; t < ntiles; t++) {
        if (t + 1 < ntiles) { issue(t + 1, (t + 1) & 1); CP_WAIT1(); }
        else                { CP_WAIT0(); }
        __syncthreads();

        const __nv_bfloat16* sKh = adsm + (t & 1) * ABUF + 0 * ATILE;
        const __nv_bfloat16* sKl = adsm + (t & 1) * ABUF + 1 * ATILE;
        const __nv_bfloat16* sVh = adsm + (t & 1) * ABUF + 2 * ATILE;
        const __nv_bfloat16* sVl = adsm + (t & 1) * ABUF + 3 * ATILE;
        const int k0 = t * 64;

        if (k0 <= wr0 + 15) {
            float s[8][4];
#pragma unroll
            for (int nt = 0; nt < 8; nt++)
#pragma unroll
                for (int j = 0; j < 4; j++) s[nt][j] = 0.f;

#pragma unroll
            for (int nt = 0; nt < 8; nt++) {
                const int cb = (nt * 8 + lr) * AP;
#pragma unroll
                for (int ks = 0; ks < 4; ks++) {
                    uint32_t bKh[2], bKl[2];
                    bKh[0] = *(const uint32_t*)&sKh[cb + ks * 16 + 2 * lc];
                    bKh[1] = *(const uint32_t*)&sKh[cb + ks * 16 + 8 + 2 * lc];
                    bKl[0] = *(const uint32_t*)&sKl[cb + ks * 16 + 2 * lc];
                    bKl[1] = *(const uint32_t*)&sKl[cb + ks * 16 + 8 + 2 * lc];
                    mma16816(s[nt], aQh[ks], bKh);
                    mma16816(s[nt], aQh[ks], bKl);
                    mma16816(s[nt], aQl[ks], bKh);
                }
            }

            if (k0 + 63 > wr0) {
                const int row0 = wr0 + lr, row1 = wr0 + 8 + lr;
#pragma unroll
                for (int nt = 0; nt < 8; nt++) {
                    int kc = k0 + nt * 8 + 2 * lc;
                    if (kc > row0)     s[nt][0] = -1e30f;
                    if (kc + 1 > row0) s[nt][1] = -1e30f;
                    if (kc > row1)     s[nt][2] = -1e30f;
                    if (kc + 1 > row1) s[nt][3] = -1e30f;
                }
            }

            float tm0 = -1e30f, tm1 = -1e30f;
#pragma unroll
            for (int nt = 0; nt < 8; nt++) {
                tm0 = fmaxf(tm0, fmaxf(s[nt][0], s[nt][1]));
                tm1 = fmaxf(tm1, fmaxf(s[nt][2], s[nt][3]));
            }
            tm0 = fmaxf(tm0, __shfl_xor_sync(0xffffffff, tm0, 1));
            tm0 = fmaxf(tm0, __shfl_xor_sync(0xffffffff, tm0, 2));
            tm1 = fmaxf(tm1, __shfl_xor_sync(0xffffffff, tm1, 1));
            tm1 = fmaxf(tm1, __shfl_xor_sync(0xffffffff, tm1, 2));

            float mn0 = fmaxf(m0, tm0), mn1 = fmaxf(m1, tm1);
            float cr0 = fexp2((m0 - mn0) * L2E);
            float cr1 = fexp2((m1 - mn1) * L2E);
            m0 = mn0; m1 = mn1;
            const float nm0 = -m0 * L2E, nm1 = -m1 * L2E;

            float ls0 = 0.f, ls1 = 0.f;
#pragma unroll
            for (int nt = 0; nt < 8; nt++) {
                s[nt][0] = fexp2(fmaf(s[nt][0], L2E, nm0));
                s[nt][1] = fexp2(fmaf(s[nt][1], L2E, nm0));
                s[nt][2] = fexp2(fmaf(s[nt][2], L2E, nm1));
                s[nt][3] = fexp2(fmaf(s[nt][3], L2E, nm1));
                ls0 += s[nt][0] + s[nt][1];
                ls1 += s[nt][2] + s[nt][3];
            }
            ls0 += __shfl_xor_sync(0xffffffff, ls0, 1);
            ls0 += __shfl_xor_sync(0xffffffff, ls0, 2);
            ls1 += __shfl_xor_sync(0xffffffff, ls1, 1);
            ls1 += __shfl_xor_sync(0xffffffff, ls1, 2);
            l0 = l0 * cr0 + ls0;
            l1 = l1 * cr1 + ls1;
#pragma unroll
            for (int nt = 0; nt < 8; nt++) {
                o[nt][0] *= cr0; o[nt][1] *= cr0;
                o[nt][2] *= cr1; o[nt][3] *= cr1;
            }

            uint32_t pH[4][4], pL[4][4];
#pragma unroll
            for (int ks = 0; ks < 4; ks++) {
                split_pack(s[2*ks][0],   s[2*ks][1],   pH[ks][0], pL[ks][0]);
                split_pack(s[2*ks][2],   s[2*ks][3],   pH[ks][1], pL[ks][1]);
                split_pack(s[2*ks+1][0], s[2*ks+1][1], pH[ks][2], pL[ks][2]);
                split_pack(s[2*ks+1][2], s[2*ks+1][3], pH[ks][3], pL[ks][3]);
            }

#pragma unroll
            for (int dt = 0; dt < 8; dt++) {
                const int cb = (dt * 8 + lr) * AP;
#pragma unroll
                for (int ks = 0; ks < 4; ks++) {
                    uint32_t bVh[2], bVl[2];
                    bVh[0] = *(const uint32_t*)&sVh[cb + ks * 16 + 2 * lc];
                    bVh[1] = *(const uint32_t*)&sVh[cb + ks * 16 + 8 + 2 * lc];
                    bVl[0] = *(const uint32_t*)&sVl[cb + ks * 16 + 2 * lc];
                    bVl[1] = *(const uint32_t*)&sVl[cb + ks * 16 + 8 + 2 * lc];
                    mma16816(o[dt], pH[ks], bVh);
                    mma16816(o[dt], pH[ks], bVl);
                    mma16816(o[dt], pL[ks], bVh);
                }
            }
        }
        __syncthreads();
    }

    const float i0 = 1.f / l0, i1 = 1.f / l1;
    const int b = bh >> 3;
    const int h = bh & 7;
    const int row0 = wr0 + lr, row1 = wr0 + 8 + lr;
    float* __restrict__ o0 = out + ((size_t)(b * SEQLEN + row0) * DOUT) + h * HDIM;
    float* __restrict__ o1 = out + ((size_t)(b * SEQLEN + row1) * DOUT) + h * HDIM;
#pragma unroll
    for (int nt = 0; nt < 8; nt++) {
        int d = nt * 8 + 2 * lc;
        *(float2*)&o0[d] = make_float2(o[nt][0] * i0, o[nt][1] * i0);
        *(float2*)&o1[d] = make_float2(o[nt][2] * i1, o[nt][3] * i1);
    }
}

// ---------------------------------------------------------------------------
extern "C" void kernel_launch(void* const* d_in, const int* in_sizes, int n_in,
                              void* d_out, int out_size)
{
    const float* Qs = (const float*)d_in[0];
    const float* Ks = (const float*)d_in[1];
    const float* Vs = (const float*)d_in[2];
    const float* WQ = (const float*)d_in[3];
    const float* WK = (const float*)d_in[4];
    const float* WV = (const float*)d_in[5];
    float* out = (float*)d_out;

    static bool attr_done = false;
    if (!attr_done) {
        cudaFuncSetAttribute(proj_mma_sync,
                             cudaFuncAttributeMaxDynamicSharedMemorySize, PROJ_DSMEM);
        cudaFuncSetAttribute(attn_mma,
                             cudaFuncAttributeMaxDynamicSharedMemorySize, ATTN_DSMEM);
        attr_done = true;
    }

    convert_x<<<dim3(MTOT * DIN / 4 / 256, 3), 256>>>(Qs, Ks, Vs);
    convert_wt<<<dim3(DOUT / 32, DIN / 32, 3), dim3(32, 8)>>>(WQ, WK, WV);
    proj_mma_sync<<<dim3(DOUT / 128, MTOT / 128, 3), 256, PROJ_DSMEM>>>();

    transpose_v<<<dim3(SEQLEN / 32, HDIM / 32, NBH), dim3(32, 8)>>>();

    attn_mma<<<dim3(SEQLEN / 128, NBH), 256, ATTN_DSMEM>>>(out);
}

// round 8
// speedup vs baseline: 3.0197x; 1.0674x over previous
#include <cuda_runtime.h>
#include <cuda_bf16.h>
#include <cstdint>

#define BATCH 8
#define SEQLEN 1024
#define DIN 512
#define NHEAD 8
#define HDIM 64
#define DOUT 512
#define MTOT (BATCH * SEQLEN)   // 8192
#define NBH (BATCH * NHEAD)     // 64

// ---------------------------------------------------------------------------
// Static device scratch (no runtime allocation allowed)
// ---------------------------------------------------------------------------
__device__ __align__(16) float g_v[NBH * SEQLEN * HDIM];

__device__ __align__(16) __nv_bfloat16 g_xhi[3 * MTOT * DIN];
__device__ __align__(16) __nv_bfloat16 g_xlo[3 * MTOT * DIN];
__device__ __align__(16) __nv_bfloat16 g_wthi[3 * DOUT * DIN];
__device__ __align__(16) __nv_bfloat16 g_wtlo[3 * DOUT * DIN];

__device__ __align__(16) __nv_bfloat16 g_qhi[NBH * SEQLEN * HDIM];
__device__ __align__(16) __nv_bfloat16 g_qlo[NBH * SEQLEN * HDIM];
__device__ __align__(16) __nv_bfloat16 g_khi[NBH * SEQLEN * HDIM];
__device__ __align__(16) __nv_bfloat16 g_klo[NBH * SEQLEN * HDIM];
__device__ __align__(16) __nv_bfloat16 g_vthi[NBH * HDIM * SEQLEN];
__device__ __align__(16) __nv_bfloat16 g_vtlo[NBH * HDIM * SEQLEN];

__device__ __forceinline__ void split_bf16(float x, __nv_bfloat16& h, __nv_bfloat16& l) {
    h = __float2bfloat16(x);
    l = __float2bfloat16(x - __bfloat162float(h));
}

__device__ __forceinline__ void mma16816(float* c, const uint32_t* a, const uint32_t* b) {
    asm volatile(
        "mma.sync.aligned.m16n8k16.row.col.f32.bf16.bf16.f32 "
        "{%0,%1,%2,%3}, {%4,%5,%6,%7}, {%8,%9}, {%0,%1,%2,%3};"
        : "+f"(c[0]), "+f"(c[1]), "+f"(c[2]), "+f"(c[3])
        : "r"(a[0]), "r"(a[1]), "r"(a[2]), "r"(a[3]), "r"(b[0]), "r"(b[1]));
}

// 16B global->shared async copy (sm_80 path, base-target safe)
__device__ __forceinline__ void cp16(void* smem_dst, const void* gsrc) {
    uint32_t sa = (uint32_t)__cvta_generic_to_shared(smem_dst);
    asm volatile("cp.async.cg.shared.global [%0], [%1], 16;" :: "r"(sa), "l"(gsrc));
}
#define CP_COMMIT() asm volatile("cp.async.commit_group;" ::: "memory")
#define CP_WAIT1()  asm volatile("cp.async.wait_group 1;" ::: "memory")
#define CP_WAIT0()  asm volatile("cp.async.wait_group 0;" ::: "memory")

// FMA-pipe exp2 (no MUFU), max rel err ~4e-5
__device__ __forceinline__ float fexp2(float t) {
    t = fmaxf(t, -126.0f);
    float z = t + 12582912.0f;
    int   i = __float_as_int(z) - 0x4B400000;
    float f = t - (z - 12582912.0f);
    float p = fmaf(f, 0.00961813f, 0.05550411f);
    p = fmaf(f, p, 0.24022651f);
    p = fmaf(f, p, 0.69314718f);
    p = fmaf(f, p, 1.0f);
    return p * __int_as_float((i + 127) << 23);
}
#define L2E 1.4426950408889634f

__device__ __forceinline__ void split_pack(float x, float y, uint32_t& hi, uint32_t& lo) {
    __nv_bfloat16 hx = __float2bfloat16(x), hy = __float2bfloat16(y);
    float rx = x - __bfloat162float(hx);
    float ry = y - __bfloat162float(hy);
    __nv_bfloat162 H(hx, hy);
    __nv_bfloat162 L(__float2bfloat16(rx), __float2bfloat16(ry));
    hi = *(uint32_t*)&H;
    lo = *(uint32_t*)&L;
}

// ---------------------------------------------------------------------------
// Conversion: X (fp32) -> bf16 hi/lo. 8 floats per thread, 16B stores.
// ---------------------------------------------------------------------------
__global__ __launch_bounds__(256) void convert_x(
    const float* __restrict__ x0, const float* __restrict__ x1,
    const float* __restrict__ x2)
{
    const int sel = blockIdx.y;
    const float* __restrict__ x = (sel == 0) ? x0 : (sel == 1) ? x1 : x2;
    const int i = blockIdx.x * 256 + threadIdx.x;          // 8-float chunk index
    const float4* xv = (const float4*)x;
    float4 a = xv[2 * i], b = xv[2 * i + 1];

    uint32_t h01, h23, h45, h67, l01, l23, l45, l67;
    split_pack(a.x, a.y, h01, l01);
    split_pack(a.z, a.w, h23, l23);
    split_pack(b.x, b.y, h45, l45);
    split_pack(b.z, b.w, h67, l67);

    const size_t e = (size_t)sel * (MTOT * DIN) + (size_t)i * 8;
    *(uint4*)&g_xhi[e] = make_uint4(h01, h23, h45, h67);
    *(uint4*)&g_xlo[e] = make_uint4(l01, l23, l45, l67);
}

__global__ __launch_bounds__(256) void convert_wt(
    const float* __restrict__ w0, const float* __restrict__ w1,
    const float* __restrict__ w2)
{
    const int sel = blockIdx.z;
    const float* __restrict__ W = (sel == 0) ? w0 : (sel == 1) ? w1 : w2;
    __shared__ float tile[32][33];
    const int n0 = blockIdx.x * 32, k0 = blockIdx.y * 32;
    const int tx = threadIdx.x, ty = threadIdx.y;
#pragma unroll
    for (int i = 0; i < 32; i += 8)
        tile[ty + i][tx] = W[(k0 + ty + i) * DOUT + n0 + tx];
    __syncthreads();
    const size_t base = (size_t)sel * (DOUT * DIN);
#pragma unroll
    for (int i = 0; i < 32; i += 8) {
        int n = ty + i;
        float v = tile[tx][n];
        __nv_bfloat16 h, l;
        split_bf16(v, h, l);
        g_wthi[base + (size_t)(n0 + n) * DIN + k0 + tx] = h;
        g_wtlo[base + (size_t)(n0 + n) * DIN + k0 + tx] = l;
    }
}

// ---------------------------------------------------------------------------
// Projection GEMM, bf16-split mma.sync, 2-stage cp.async double buffer.
// ---------------------------------------------------------------------------
#define PADK 40
#define PTILE (128 * PADK)
#define PBUF  (4 * PTILE)
#define PROJ_DSMEM (2 * PBUF * 2)

__global__ __launch_bounds__(256) void proj_mma_sync()
{
    extern __shared__ __align__(16) __nv_bfloat16 dsm[];

    const int sel = blockIdx.z;
    const int n0  = blockIdx.x * 128;
    const int m0  = blockIdx.y * 128;
    const int tid = threadIdx.x;
    const int w   = tid >> 5;
    const int lane = tid & 31;
    const int wm = w >> 2, wn = w & 3;
    const int lr = lane >> 2, lc = lane & 3;

    const __nv_bfloat16* __restrict__ Ahp = g_xhi + (size_t)sel * (MTOT * DIN);
    const __nv_bfloat16* __restrict__ Alp = g_xlo + (size_t)sel * (MTOT * DIN);
    const __nv_bfloat16* __restrict__ Bhp = g_wthi + (size_t)sel * (DOUT * DIN);
    const __nv_bfloat16* __restrict__ Blp = g_wtlo + (size_t)sel * (DOUT * DIN);

    const int r0 = tid >> 2, c0 = (tid & 3) * 8;
    const int r1 = (tid + 256) >> 2, c1 = ((tid + 256) & 3) * 8;

    auto issue = [&](int slab, int buf) {
        const int kk = slab * 32;
        __nv_bfloat16* base = dsm + buf * PBUF;
        const size_t ga0 = (size_t)(m0 + r0) * DIN + kk + c0;
        const size_t gb0 = (size_t)(n0 + r0) * DIN + kk + c0;
        const size_t ga1 = (size_t)(m0 + r1) * DIN + kk + c1;
        const size_t gb1 = (size_t)(n0 + r1) * DIN + kk + c1;
        cp16(base + 0 * PTILE + r0 * PADK + c0, Ahp + ga0);
        cp16(base + 1 * PTILE + r0 * PADK + c0, Alp + ga0);
        cp16(base + 2 * PTILE + r0 * PADK + c0, Bhp + gb0);
        cp16(base + 3 * PTILE + r0 * PADK + c0, Blp + gb0);
        cp16(base + 0 * PTILE + r1 * PADK + c1, Ahp + ga1);
        cp16(base + 1 * PTILE + r1 * PADK + c1, Alp + ga1);
        cp16(base + 2 * PTILE + r1 * PADK + c1, Bhp + gb1);
        cp16(base + 3 * PTILE + r1 * PADK + c1, Blp + gb1);
        CP_COMMIT();
    };

    float acc[4][4][4];
#pragma unroll
    for (int i = 0; i < 4; i++)
#pragma unroll
        for (int j = 0; j < 4; j++)
#pragma unroll
            for (int r = 0; r < 4; r++) acc[i][j][r] = 0.f;

    issue(0, 0);

    for (int s = 0; s < DIN / 32; s++) {
        if (s + 1 < DIN / 32) { issue(s + 1, (s + 1) & 1); CP_WAIT1(); }
        else                  { CP_WAIT0(); }
        __syncthreads();

        const __nv_bfloat16* sAh = dsm + (s & 1) * PBUF + 0 * PTILE;
        const __nv_bfloat16* sAl = dsm + (s & 1) * PBUF + 1 * PTILE;
        const __nv_bfloat16* sBh = dsm + (s & 1) * PBUF + 2 * PTILE;
        const __nv_bfloat16* sBl = dsm + (s & 1) * PBUF + 3 * PTILE;

#pragma unroll
        for (int ks = 0; ks < 2; ks++) {
            const int k0 = ks * 16;
            uint32_t bH[4][2], bL[4][2];
#pragma unroll
            for (int nt = 0; nt < 4; nt++) {
                int cb = wn * 32 + nt * 8 + lr;
                bH[nt][0] = *(const uint32_t*)&sBh[cb * PADK + k0 + lc * 2];
                bH[nt][1] = *(const uint32_t*)&sBh[cb * PADK + k0 + 8 + lc * 2];
                bL[nt][0] = *(const uint32_t*)&sBl[cb * PADK + k0 + lc * 2];
                bL[nt][1] = *(const uint32_t*)&sBl[cb * PADK + k0 + 8 + lc * 2];
            }
            uint32_t af[4][4];
#pragma unroll
            for (int mt = 0; mt < 4; mt++) {
                int rb = wm * 64 + mt * 16 + lr;
                af[mt][0] = *(const uint32_t*)&sAh[rb * PADK + k0 + lc * 2];
                af[mt][1] = *(const uint32_t*)&sAh[(rb + 8) * PADK + k0 + lc * 2];
                af[mt][2] = *(const uint32_t*)&sAh[rb * PADK + k0 + 8 + lc * 2];
                af[mt][3] = *(const uint32_t*)&sAh[(rb + 8) * PADK + k0 + 8 + lc * 2];
            }
#pragma unroll
            for (int mt = 0; mt < 4; mt++)
#pragma unroll
                for (int nt = 0; nt < 4; nt++) {
                    mma16816(acc[mt][nt], af[mt], bH[nt]);
                    mma16816(acc[mt][nt], af[mt], bL[nt]);
                }
#pragma unroll
            for (int mt = 0; mt < 4; mt++) {
                int rb = wm * 64 + mt * 16 + lr;
                af[mt][0] = *(const uint32_t*)&sAl[rb * PADK + k0 + lc * 2];
                af[mt][1] = *(const uint32_t*)&sAl[(rb + 8) * PADK + k0 + lc * 2];
                af[mt][2] = *(const uint32_t*)&sAl[rb * PADK + k0 + 8 + lc * 2];
                af[mt][3] = *(const uint32_t*)&sAl[(rb + 8) * PADK + k0 + 8 + lc * 2];
            }
#pragma unroll
            for (int mt = 0; mt < 4; mt++)
#pragma unroll
                for (int nt = 0; nt < 4; nt++)
                    mma16816(acc[mt][nt], af[mt], bH[nt]);
        }
        __syncthreads();
    }

    if (sel < 2) {
        const float scale = (sel == 0) ? 0.125f : 1.0f;
        __nv_bfloat16* __restrict__ dh = (sel == 0) ? g_qhi : g_khi;
        __nv_bfloat16* __restrict__ dl = (sel == 0) ? g_qlo : g_klo;
#pragma unroll
        for (int mt = 0; mt < 4; mt++) {
#pragma unroll
            for (int half = 0; half < 2; half++) {
                int m = m0 + wm * 64 + mt * 16 + half * 8 + lr;
                int b = m >> 10;
                int l = m & 1023;
#pragma unroll
                for (int nt = 0; nt < 4; nt++) {
                    int n = n0 + wn * 32 + nt * 8 + lc * 2;
                    int h = n >> 6;
                    int d = n & 63;
                    uint32_t hi, lo;
                    split_pack(acc[mt][nt][half * 2 + 0] * scale,
                               acc[mt][nt][half * 2 + 1] * scale, hi, lo);
                    size_t off = (((size_t)(b * NHEAD + h) * SEQLEN) + l) * HDIM + d;
                    *(uint32_t*)&dh[off] = hi;
                    *(uint32_t*)&dl[off] = lo;
                }
            }
        }
    } else {
#pragma unroll
        for (int mt = 0; mt < 4; mt++) {
#pragma unroll
            for (int half = 0; half < 2; half++) {
                int m = m0 + wm * 64 + mt * 16 + half * 8 + lr;
                int b = m >> 10;
                int l = m & 1023;
#pragma unroll
                for (int nt = 0; nt < 4; nt++) {
                    int n = n0 + wn * 32 + nt * 8 + lc * 2;
                    int h = n >> 6;
                    int d = n & 63;
                    float2 o = make_float2(acc[mt][nt][half * 2 + 0],
                                           acc[mt][nt][half * 2 + 1]);
                    *(float2*)&g_v[(((size_t)(b * NHEAD + h) * SEQLEN) + l) * HDIM + d] = o;
                }
            }
        }
    }
}

// ---------------------------------------------------------------------------
// Prep: V fp32 [bh][l][64] -> transposed bf16 hi/lo [bh][d][1024]
// ---------------------------------------------------------------------------
__global__ __launch_bounds__(256) void transpose_v()
{
    const int bh = blockIdx.z;
    const int l0 = blockIdx.x * 32;
    const int d0 = blockIdx.y * 32;
    __shared__ float tile[32][33];
    const int tx = threadIdx.x, ty = threadIdx.y;
    const float* __restrict__ src = g_v + (size_t)bh * SEQLEN * HDIM;
#pragma unroll
    for (int i = 0; i < 32; i += 8)
        tile[ty + i][tx] = src[(l0 + ty + i) * HDIM + d0 + tx];
    __syncthreads();
    const size_t base = (size_t)bh * (HDIM * SEQLEN);
#pragma unroll
    for (int i = 0; i < 32; i += 8) {
        int d = ty + i;
        float v = tile[tx][d];
        __nv_bfloat16 h, l;
        split_bf16(v, h, l);
        g_vthi[base + (size_t)(d0 + d) * SEQLEN + l0 + tx] = h;
        g_vtlo[base + (size_t)(d0 + d) * SEQLEN + l0 + tx] = l;
    }
}

// ---------------------------------------------------------------------------
// Flash attention on tensor cores, 2-stage cp.async double buffer.
// 1-D grid sorted longest-work-first; warp-uniform skip of masked MMA chunks.
// ---------------------------------------------------------------------------
#define AP 72
#define ATILE (64 * AP)
#define ABUF  (4 * ATILE)
#define ATTN_DSMEM (2 * ABUF * 2)

__global__ __launch_bounds__(256) void attn_mma(float* __restrict__ out)
{
    extern __shared__ __align__(16) __nv_bfloat16 adsm[];

    // longest-first schedule: qb descending as blockIdx.x grows slowest
    const int bh  = blockIdx.x & (NBH - 1);
    const int qb  = (SEQLEN / 128 - 1) - (blockIdx.x >> 6);
    const int q0  = qb * 128;
    const int tid = threadIdx.x;
    const int w    = tid >> 5;
    const int lane = tid & 31;
    const int lr = lane >> 2, lc = lane & 3;
    const int wr0 = q0 + w * 16;
    const int wlast = wr0 + 15;            // last q row of this warp

    const size_t bhoff = (size_t)bh * (SEQLEN * HDIM);
    const __nv_bfloat16* __restrict__ Kh = g_khi + bhoff;
    const __nv_bfloat16* __restrict__ Kl = g_klo + bhoff;
    const __nv_bfloat16* __restrict__ Vh = g_vthi + bhoff;
    const __nv_bfloat16* __restrict__ Vl = g_vtlo + bhoff;

    const int r0 = tid >> 3, c0 = (tid & 7) * 8;
    const int r1 = (tid + 256) >> 3, c1 = ((tid + 256) & 7) * 8;

    auto issue = [&](int tileidx, int buf) {
        const int k0 = tileidx * 64;
        __nv_bfloat16* base = adsm + buf * ABUF;
        cp16(base + 0 * ATILE + r0 * AP + c0, Kh + (size_t)(k0 + r0) * HDIM + c0);
        cp16(base + 1 * ATILE + r0 * AP + c0, Kl + (size_t)(k0 + r0) * HDIM + c0);
        cp16(base + 2 * ATILE + r0 * AP + c0, Vh + (size_t)r0 * SEQLEN + k0 + c0);
        cp16(base + 3 * ATILE + r0 * AP + c0, Vl + (size_t)r0 * SEQLEN + k0 + c0);
        cp16(base + 0 * ATILE + r1 * AP + c1, Kh + (size_t)(k0 + r1) * HDIM + c1);
        cp16(base + 1 * ATILE + r1 * AP + c1, Kl + (size_t)(k0 + r1) * HDIM + c1);
        cp16(base + 2 * ATILE + r1 * AP + c1, Vh + (size_t)r1 * SEQLEN + k0 + c1);
        cp16(base + 3 * ATILE + r1 * AP + c1, Vl + (size_t)r1 * SEQLEN + k0 + c1);
        CP_COMMIT();
    };

    uint32_t aQh[4][4], aQl[4][4];
    {
        const __nv_bfloat16* __restrict__ Qh = g_qhi + bhoff;
        const __nv_bfloat16* __restrict__ Ql = g_qlo + bhoff;
#pragma unroll
        for (int ks = 0; ks < 4; ks++) {
            int k = ks * 16 + 2 * lc;
            aQh[ks][0] = *(const uint32_t*)&Qh[(wr0 + lr) * HDIM + k];
            aQh[ks][1] = *(const uint32_t*)&Qh[(wr0 + 8 + lr) * HDIM + k];
            aQh[ks][2] = *(const uint32_t*)&Qh[(wr0 + lr) * HDIM + k + 8];
            aQh[ks][3] = *(const uint32_t*)&Qh[(wr0 + 8 + lr) * HDIM + k + 8];
            aQl[ks][0] = *(const uint32_t*)&Ql[(wr0 + lr) * HDIM + k];
            aQl[ks][1] = *(const uint32_t*)&Ql[(wr0 + 8 + lr) * HDIM + k];
            aQl[ks][2] = *(const uint32_t*)&Ql[(wr0 + lr) * HDIM + k + 8];
            aQl[ks][3] = *(const uint32_t*)&Ql[(wr0 + 8 + lr) * HDIM + k + 8];
        }
    }

    float o[8][4];
#pragma unroll
    for (int nt = 0; nt < 8; nt++)
#pragma unroll
        for (int j = 0; j < 4; j++) o[nt][j] = 0.f;
    float m0 = -1e30f, m1 = -1e30f, l0 = 0.f, l1 = 0.f;

    const int ntiles = (q0 + 128) / 64;
    issue(0, 0);

    for (int t = 0; t < ntiles; t++) {
        if (t + 1 < ntiles) { issue(t + 1, (t + 1) & 1); CP_WAIT1(); }
        else                { CP_WAIT0(); }
        __syncthreads();

        const __nv_bfloat16* sKh = adsm + (t & 1) * ABUF + 0 * ATILE;
        const __nv_bfloat16* sKl = adsm + (t & 1) * ABUF + 1 * ATILE;
        const __nv_bfloat16* sVh = adsm + (t & 1) * ABUF + 2 * ATILE;
        const __nv_bfloat16* sVl = adsm + (t & 1) * ABUF + 3 * ATILE;
        const int k0 = t * 64;

        if (k0 <= wlast) {
            float s[8][4];
#pragma unroll
            for (int nt = 0; nt < 8; nt++)
#pragma unroll
                for (int j = 0; j < 4; j++) s[nt][j] = 0.f;

#pragma unroll
            for (int nt = 0; nt < 8; nt++) {
                if (k0 + nt * 8 <= wlast) {   // warp-uniform: chunk has live keys
                    const int cb = (nt * 8 + lr) * AP;
#pragma unroll
                    for (int ks = 0; ks < 4; ks++) {
                        uint32_t bKh[2], bKl[2];
                        bKh[0] = *(const uint32_t*)&sKh[cb + ks * 16 + 2 * lc];
                        bKh[1] = *(const uint32_t*)&sKh[cb + ks * 16 + 8 + 2 * lc];
                        bKl[0] = *(const uint32_t*)&sKl[cb + ks * 16 + 2 * lc];
                        bKl[1] = *(const uint32_t*)&sKl[cb + ks * 16 + 8 + 2 * lc];
                        mma16816(s[nt], aQh[ks], bKh);
                        mma16816(s[nt], aQh[ks], bKl);
                        mma16816(s[nt], aQl[ks], bKh);
                    }
                }
            }

            if (k0 + 63 > wr0) {
                const int row0 = wr0 + lr, row1 = wr0 + 8 + lr;
#pragma unroll
                for (int nt = 0; nt < 8; nt++) {
                    int kc = k0 + nt * 8 + 2 * lc;
                    if (kc > row0)     s[nt][0] = -1e30f;
                    if (kc + 1 > row0) s[nt][1] = -1e30f;
                    if (kc > row1)     s[nt][2] = -1e30f;
                    if (kc + 1 > row1) s[nt][3] = -1e30f;
                }
            }

            float tm0 = -1e30f, tm1 = -1e30f;
#pragma unroll
            for (int nt = 0; nt < 8; nt++) {
                tm0 = fmaxf(tm0, fmaxf(s[nt][0], s[nt][1]));
                tm1 = fmaxf(tm1, fmaxf(s[nt][2], s[nt][3]));
            }
            tm0 = fmaxf(tm0, __shfl_xor_sync(0xffffffff, tm0, 1));
            tm0 = fmaxf(tm0, __shfl_xor_sync(0xffffffff, tm0, 2));
            tm1 = fmaxf(tm1, __shfl_xor_sync(0xffffffff, tm1, 1));
            tm1 = fmaxf(tm1, __shfl_xor_sync(0xffffffff, tm1, 2));

            float mn0 = fmaxf(m0, tm0), mn1 = fmaxf(m1, tm1);
            float cr0 = fexp2((m0 - mn0) * L2E);
            float cr1 = fexp2((m1 - mn1) * L2E);
            m0 = mn0; m1 = mn1;
            const float nm0 = -m0 * L2E, nm1 = -m1 * L2E;

            float ls0 = 0.f, ls1 = 0.f;
#pragma unroll
            for (int nt = 0; nt < 8; nt++) {
                s[nt][0] = fexp2(fmaf(s[nt][0], L2E, nm0));
                s[nt][1] = fexp2(fmaf(s[nt][1], L2E, nm0));
                s[nt][2] = fexp2(fmaf(s[nt][2], L2E, nm1));
                s[nt][3] = fexp2(fmaf(s[nt][3], L2E, nm1));
                ls0 += s[nt][0] + s[nt][1];
                ls1 += s[nt][2] + s[nt][3];
            }
            ls0 += __shfl_xor_sync(0xffffffff, ls0, 1);
            ls0 += __shfl_xor_sync(0xffffffff, ls0, 2);
            ls1 += __shfl_xor_sync(0xffffffff, ls1, 1);
            ls1 += __shfl_xor_sync(0xffffffff, ls1, 2);
            l0 = l0 * cr0 + ls0;
            l1 = l1 * cr1 + ls1;
#pragma unroll
            for (int nt = 0; nt < 8; nt++) {
                o[nt][0] *= cr0; o[nt][1] *= cr0;
                o[nt][2] *= cr1; o[nt][3] *= cr1;
            }

            uint32_t pH[4][4], pL[4][4];
#pragma unroll
            for (int ks = 0; ks < 4; ks++) {
                if (k0 + ks * 16 <= wlast) {
                    split_pack(s[2*ks][0],   s[2*ks][1],   pH[ks][0], pL[ks][0]);
                    split_pack(s[2*ks][2],   s[2*ks][3],   pH[ks][1], pL[ks][1]);
                    split_pack(s[2*ks+1][0], s[2*ks+1][1], pH[ks][2], pL[ks][2]);
                    split_pack(s[2*ks+1][2], s[2*ks+1][3], pH[ks][3], pL[ks][3]);
                }
            }

#pragma unroll
            for (int dt = 0; dt < 8; dt++) {
                const int cb = (dt * 8 + lr) * AP;
#pragma unroll
                for (int ks = 0; ks < 4; ks++) {
                    if (k0 + ks * 16 <= wlast) {   // warp-uniform: live P chunk
                        uint32_t bVh[2], bVl[2];
                        bVh[0] = *(const uint32_t*)&sVh[cb + ks * 16 + 2 * lc];
                        bVh[1] = *(const uint32_t*)&sVh[cb + ks * 16 + 8 + 2 * lc];
                        bVl[0] = *(const uint32_t*)&sVl[cb + ks * 16 + 2 * lc];
                        bVl[1] = *(const uint32_t*)&sVl[cb + ks * 16 + 8 + 2 * lc];
                        mma16816(o[dt], pH[ks], bVh);
                        mma16816(o[dt], pH[ks], bVl);
                        mma16816(o[dt], pL[ks], bVh);
                    }
                }
            }
        }
        __syncthreads();
    }

    const float i0 = 1.f / l0, i1 = 1.f / l1;
    const int b = bh >> 3;
    const int h = bh & 7;
    const int row0 = wr0 + lr, row1 = wr0 + 8 + lr;
    float* __restrict__ o0 = out + ((size_t)(b * SEQLEN + row0) * DOUT) + h * HDIM;
    float* __restrict__ o1 = out + ((size_t)(b * SEQLEN + row1) * DOUT) + h * HDIM;
#pragma unroll
    for (int nt = 0; nt < 8; nt++) {
        int d = nt * 8 + 2 * lc;
        *(float2*)&o0[d] = make_float2(o[nt][0] * i0, o[nt][1] * i0);
        *(float2*)&o1[d] = make_float2(o[nt][2] * i1, o[nt][3] * i1);
    }
}

// ---------------------------------------------------------------------------
extern "C" void kernel_launch(void* const* d_in, const int* in_sizes, int n_in,
                              void* d_out, int out_size)
{
    const float* Qs = (const float*)d_in[0];
    const float* Ks = (const float*)d_in[1];
    const float* Vs = (const float*)d_in[2];
    const float* WQ = (const float*)d_in[3];
    const float* WK = (const float*)d_in[4];
    const float* WV = (const float*)d_in[5];
    float* out = (float*)d_out;

    static bool attr_done = false;
    if (!attr_done) {
        cudaFuncSetAttribute(proj_mma_sync,
                             cudaFuncAttributeMaxDynamicSharedMemorySize, PROJ_DSMEM);
        cudaFuncSetAttribute(attn_mma,
                             cudaFuncAttributeMaxDynamicSharedMemorySize, ATTN_DSMEM);
        attr_done = true;
    }

    convert_x<<<dim3(MTOT * DIN / 8 / 256, 3), 256>>>(Qs, Ks, Vs);
    convert_wt<<<dim3(DOUT / 32, DIN / 32, 3), dim3(32, 8)>>>(WQ, WK, WV);
    proj_mma_sync<<<dim3(DOUT / 128, MTOT / 128, 3), 256, PROJ_DSMEM>>>();

    transpose_v<<<dim3(SEQLEN / 32, HDIM / 32, NBH), dim3(32, 8)>>>();

    attn_mma<<<(SEQLEN / 128) * NBH, 256, ATTN_DSMEM>>>(out);
}